// round 11
// baseline (speedup 1.0000x reference)
#include <cuda_runtime.h>
#include <cuda_fp16.h>
#include <cstdint>
#include <math.h>

#define D   128
#define N   256
#define BSZ 2
#define KNB 3
#define EPSF 1e-5f
#define NEG_INF (-3.402823466e38f)

// ---------------- scratch (no allocs allowed) ----------------
__device__ float g_P [2][BSZ][N][D];
__device__ float g_Q [2][BSZ][N][D];
__device__ float g_A [2][BSZ][N][D];
__device__ int   g_Idx[2][BSZ][N][KNB];
__device__ float g_S [2][BSZ][N][N];   // [0]=anchor sigmoid, [1]=raw-pair sigmoid
__device__ __half g_Wh[D * D];         // W0^T as fp16: g_Wh[d*128 + k] = cw0[k*128 + d]

// ---------------- mma.sync / ldmatrix helpers (fp16, m16n8k16) ----------------
__device__ __forceinline__ void mma16(float c[4], const uint32_t a[4],
                                      uint32_t b0, uint32_t b1){
    asm volatile(
        "mma.sync.aligned.m16n8k16.row.col.f32.f16.f16.f32 "
        "{%0,%1,%2,%3}, {%4,%5,%6,%7}, {%8,%9}, {%0,%1,%2,%3};\n"
        : "+f"(c[0]), "+f"(c[1]), "+f"(c[2]), "+f"(c[3])
        : "r"(a[0]), "r"(a[1]), "r"(a[2]), "r"(a[3]), "r"(b0), "r"(b1));
}

__device__ __forceinline__ void ldm4(uint32_t r[4], uint32_t addr){
    asm volatile("ldmatrix.sync.aligned.m8n8.x4.shared.b16 {%0,%1,%2,%3}, [%4];"
        : "=r"(r[0]), "=r"(r[1]), "=r"(r[2]), "=r"(r[3]) : "r"(addr));
}

__device__ __forceinline__ uint32_t ad2(uint32_t a, uint32_t b){
    __half2 ha = *reinterpret_cast<__half2*>(&a);
    __half2 hb = *reinterpret_cast<__half2*>(&b);
    __half2 r  = __habs2(__hsub2(ha, hb));
    return *reinterpret_cast<uint32_t*>(&r);
}

// smem layout for cls tiles (bytes)
#define OFF_PS   0
#define OFF_PT   512
#define OFF_PW   1024
#define OFF_LG   1536     // 128 floats
#define OFF_US   2048     // Ush2: 16 x 68 uint32 = 4352
#define OFF_VS   6400     // Vsh2:  8 x 68 uint32 = 2176
#define OFF_WT   8704     // Wt swizzled fp16 [128 d][128 k] = 32768
#define OFF_XS   41472    // Xs swizzled fp16 [128 pair][128 k] = 32768
#define SMEM_BYTES 74240
#define UPAD 68

// ---------------- cls tile: 128 pairs (16 i x 8 j), 32p x 64d warp tiles ----------------
template<bool FROM_CW0>
__device__ __forceinline__ void cls_tile(
    const float* __restrict__ Ubase, const float* __restrict__ Vbase,
    int i0, int j0, float* __restrict__ Sout,
    const float* __restrict__ cw0,
    const float* __restrict__ cb0, const float* __restrict__ cg,
    const float* __restrict__ cbe, const float* __restrict__ cm,
    const float* __restrict__ cv,  const float* __restrict__ cw1,
    const float* __restrict__ cb1, char* smb)
{
    float*    ps    = (float*)   (smb + OFF_PS);
    float*    pt    = (float*)   (smb + OFF_PT);
    float*    pw1   = (float*)   (smb + OFF_PW);
    float*    logit = (float*)   (smb + OFF_LG);
    uint32_t* Ush2  = (uint32_t*)(smb + OFF_US);
    uint32_t* Vsh2  = (uint32_t*)(smb + OFF_VS);
    char*     Xs    = smb + OFF_XS;
    uint32_t smem_base = (uint32_t)__cvta_generic_to_shared(smb);
    uint32_t wt_s = smem_base + OFF_WT;
    uint32_t xs_s = smem_base + OFF_XS;

    int t = threadIdx.x;
    int lane = t & 31, warp = t >> 5;
    int gid = lane >> 2, tig = lane & 3;
    int pg = warp >> 1, dg = warp & 1;        // 4 pair-groups (32 pairs) x 2 d-groups (64 d)

    // stage swizzled Wt
    if (FROM_CW0){
        // fp32 -> fp16 (self-sufficient; no g_Wh dependency). 32 half2 per thread.
        for (int e = t; e < 64 * 128; e += 256){
            int k2 = e >> 7, d = e & 127;
            float w0 = cw0[(2 * k2) * D + d];
            float w1 = cw0[(2 * k2 + 1) * D + d];
            __half2 h = __floats2half2_rn(w0, w1);
            int k = 2 * k2, ck = k >> 3;
            *(uint32_t*)(smb + OFF_WT + d * 256 + ((ck ^ (d & 7)) << 4) + (k & 7) * 2)
                = *(uint32_t*)&h;
        }
    } else {
        #pragma unroll
        for (int i = 0; i < 8; i++){
            int e = t + i * 256;              // 2048 16B chunks
            int d = e >> 4, ck = e & 15;
            uint4 v = *(const uint4*)(g_Wh + d * D + ck * 8);
            *(uint4*)(smb + OFF_WT + d * 256 + ((ck ^ (d & 7)) << 4)) = v;
        }
    }
    if (t < D){
        float s = cg[t] * rsqrtf(cv[t] + EPSF);
        ps[t]  = s;
        pt[t]  = (cb0[t] - cm[t]) * s + cbe[t];
        pw1[t] = cw1[t];
    }
    if (t < 128) logit[t] = cb1[0];
    // stage U (16 rows) / V (8 rows) as half2 (coalesced float2 LDG)
    for (int e = t; e < 16 * 64; e += 256){
        int r = e >> 6, c = e & 63;
        float2 fu = *(const float2*)(Ubase + (i0 + r) * D + 2 * c);
        __half2 hu = __floats2half2_rn(fu.x, fu.y);
        Ush2[r * UPAD + c] = *(uint32_t*)&hu;
    }
    for (int e = t; e < 8 * 64; e += 256){
        int r = e >> 6, c = e & 63;
        float2 fv = *(const float2*)(Vbase + (j0 + r) * D + 2 * c);
        __half2 hv = __floats2half2_rn(fv.x, fv.y);
        Vsh2[r * UPAD + c] = *(uint32_t*)&hv;
    }
    __syncthreads();

    // build X = |U_i - V_j| into swizzled tile: 8 STS.128 per thread
    {
        int g2 = t >> 4, kO = t & 15;
        int ib = (g2 >> 1) * 2;
        int jb = (g2 & 1) * 4;
        uint4 u0 = *(const uint4*)(Ush2 +  ib      * UPAD + kO * 4);
        uint4 u1 = *(const uint4*)(Ush2 + (ib + 1) * UPAD + kO * 4);
        #pragma unroll
        for (int jj = 0; jj < 4; jj++){
            uint4 v = *(const uint4*)(Vsh2 + (jb + jj) * UPAD + kO * 4);
            uint4 x0, x1;
            x0.x = ad2(u0.x, v.x); x0.y = ad2(u0.y, v.y);
            x0.z = ad2(u0.z, v.z); x0.w = ad2(u0.w, v.w);
            x1.x = ad2(u1.x, v.x); x1.y = ad2(u1.y, v.y);
            x1.z = ad2(u1.z, v.z); x1.w = ad2(u1.w, v.w);
            int p0 =  ib      * 8 + jb + jj;
            int p1 = (ib + 1) * 8 + jb + jj;
            *(uint4*)(Xs + p0 * 256 + ((kO ^ (p0 & 7)) << 4)) = x0;
            *(uint4*)(Xs + p1 * 256 + ((kO ^ (p1 & 7)) << 4)) = x1;
        }
    }
    __syncthreads();

    // A (Xs) ldmatrix: two m-tiles (16 pairs each)
    int a_row0 = pg * 32 + (lane & 15);
    int a_row1 = a_row0 + 16;
    uint32_t a0_base = xs_s + a_row0 * 256;
    uint32_t a1_base = xs_s + a_row1 * 256;
    int a0_r7 = a_row0 & 7, a_hi = lane >> 4;
    int a1_r7 = a_row1 & 7;
    // B (Wt)
    int b_row_off = (lane & 7) + (((lane >> 4) & 1) << 3);
    int b_khi = (lane >> 3) & 1;
    uint32_t bw_base[4]; int bw_r7[4];
    #pragma unroll
    for (int ng = 0; ng < 4; ng++){
        int row = dg * 64 + ng * 16 + b_row_off;
        bw_base[ng] = wt_s + row * 256;
        bw_r7[ng]   = row & 7;
    }

    float cacc[2][8][4];
    #pragma unroll
    for (int mt = 0; mt < 2; mt++)
        #pragma unroll
        for (int nt = 0; nt < 8; nt++)
            #pragma unroll
            for (int q = 0; q < 4; q++) cacc[mt][nt][q] = 0.f;

    #pragma unroll 2
    for (int ks = 0; ks < 8; ks++){
        int ck = 2 * ks;
        uint32_t aX0[4], aX1[4];
        ldm4(aX0, a0_base + (((ck + a_hi) ^ a0_r7) << 4));
        ldm4(aX1, a1_base + (((ck + a_hi) ^ a1_r7) << 4));
        #pragma unroll
        for (int ng = 0; ng < 4; ng++){
            uint32_t bW[4];
            ldm4(bW, bw_base[ng] + (((ck + b_khi) ^ bw_r7[ng]) << 4));
            mma16(cacc[0][ng * 2],     aX0, bW[0], bW[1]);
            mma16(cacc[0][ng * 2 + 1], aX0, bW[2], bW[3]);
            mma16(cacc[1][ng * 2],     aX1, bW[0], bW[1]);
            mma16(cacc[1][ng * 2 + 1], aX1, bW[2], bW[3]);
        }
    }

    // epilogue
    #pragma unroll
    for (int mt = 0; mt < 2; mt++){
        float l0 = 0.f, l1 = 0.f;
        #pragma unroll
        for (int nt = 0; nt < 8; nt++){
            int d0 = dg * 64 + (nt >> 1) * 16 + (nt & 1) * 8 + 2 * tig;
            float s0 = ps[d0], t0 = pt[d0], w0 = pw1[d0];
            float s1 = ps[d0 + 1], t1 = pt[d0 + 1], w1 = pw1[d0 + 1];
            float* c = cacc[mt][nt];
            l0 += fmaxf(c[0] * s0 + t0, 0.f) * w0 + fmaxf(c[1] * s1 + t1, 0.f) * w1;
            l1 += fmaxf(c[2] * s0 + t0, 0.f) * w0 + fmaxf(c[3] * s1 + t1, 0.f) * w1;
        }
        l0 += __shfl_xor_sync(0xffffffffu, l0, 1);
        l0 += __shfl_xor_sync(0xffffffffu, l0, 2);
        l1 += __shfl_xor_sync(0xffffffffu, l1, 1);
        l1 += __shfl_xor_sync(0xffffffffu, l1, 2);
        if (tig == 0){
            atomicAdd(&logit[pg * 32 + mt * 16 + gid],     l0);
            atomicAdd(&logit[pg * 32 + mt * 16 + gid + 8], l1);
        }
    }
    __syncthreads();
    if (t < 128){
        float sc = 1.f / (1.f + expf(-logit[t]));
        Sout[(i0 + (t >> 3)) * N + (j0 + (t & 7))] = sc;
    }
}

// ---------------- proj part (256 threads): P/Q for 4 rows ----------------
__device__ __forceinline__ void proj_part(int grp,
        const float* __restrict__ f1, const float* __restrict__ f2,
        const float* __restrict__ sw0, char* smb){
    float* fs = (float*)smb;                  // 4*128 floats
    int t = threadIdx.x;
    int f = grp >> 7, b = (grp >> 6) & 1, i0 = (grp & 63) * 4;
    const float* featb = (f == 0 ? f1 : f2) + b * N * D;
    for (int e = t; e < 4 * D; e += 256) fs[e] = featb[i0 * D + e];
    __syncthreads();
    int d = t & 127, which = t >> 7;
    const float* wb = sw0 + which * D * D + d;
    float a0 = 0.f, a1 = 0.f, a2 = 0.f, a3 = 0.f;
    #pragma unroll 8
    for (int c = 0; c < D; c++){
        float w = wb[c * D];
        a0 = fmaf(fs[c],           w, a0);
        a1 = fmaf(fs[D + c],       w, a1);
        a2 = fmaf(fs[2 * D + c],   w, a2);
        a3 = fmaf(fs[3 * D + c],   w, a3);
    }
    float* dst = which ? &g_Q[f][b][0][0] : &g_P[f][b][0][0];
    dst[(i0    ) * D + d] = a0;
    dst[(i0 + 1) * D + d] = a1;
    dst[(i0 + 2) * D + d] = a2;
    dst[(i0 + 3) * D + d] = a3;
}

// ---------------- topk part (256 threads): 4 i's -> top3 -> absorb + indices ----------------
__device__ __forceinline__ void topk_part(int gb,
        const float* __restrict__ f1, const float* __restrict__ f2,
        const float* __restrict__ sb0, const float* __restrict__ sg,
        const float* __restrict__ sbe, const float* __restrict__ smn,
        const float* __restrict__ sv,  const float* __restrict__ sw1,
        char* smb){
    int f = gb >> 7, b = (gb >> 6) & 1, i0 = (gb & 63) * 4;
    float* Ps  = (float*)smb;                 // [4][128]
    float* ss  = (float*)(smb + 2048);
    float* tt  = (float*)(smb + 2560);
    float* w1s = (float*)(smb + 3072);
    float* wv  = (float*)(smb + 3584);        // 8
    int*   wi  = (int*)  (smb + 3616);        // 8
    int*   bidx= (int*)  (smb + 3648);        // [4][KNB]
    int t = threadIdx.x, lane = t & 31, warp = t >> 5;
    if (t < D){
        float s = sg[t] * rsqrtf(sv[t] + EPSF);
        ss[t]  = s;
        tt[t]  = (sb0[t] - smn[t]) * s + sbe[t];
        w1s[t] = sw1[t];
        #pragma unroll
        for (int r = 0; r < 4; r++) Ps[r * D + t] = g_P[f][b][i0 + r][t];
    }
    __syncthreads();
    const float* Qrow = &g_Q[f][b][t][0];
    float simv[4] = {0.f, 0.f, 0.f, 0.f};
    #pragma unroll 4
    for (int d = 0; d < D; d += 4){
        float4 q = *(const float4*)(Qrow + d);
        float s0 = ss[d], s1 = ss[d+1], s2 = ss[d+2], s3 = ss[d+3];
        float t0 = tt[d], t1 = tt[d+1], t2 = tt[d+2], t3 = tt[d+3];
        float w0 = w1s[d], w1 = w1s[d+1], w2 = w1s[d+2], w3 = w1s[d+3];
        #pragma unroll
        for (int r = 0; r < 4; r++){
            float h0 = (Ps[r * D + d]   + q.x) * s0 + t0;
            float h1 = (Ps[r * D + d+1] + q.y) * s1 + t1;
            float h2 = (Ps[r * D + d+2] + q.z) * s2 + t2;
            float h3 = (Ps[r * D + d+3] + q.w) * s3 + t3;
            simv[r] += fmaxf(h0, 0.f) * w0 + fmaxf(h1, 0.f) * w1
                     + fmaxf(h2, 0.f) * w2 + fmaxf(h3, 0.f) * w3;
        }
    }
    #pragma unroll
    for (int r = 0; r < 4; r++) if (t == i0 + r) simv[r] = NEG_INF;

    for (int r = 0; r < 4; r++){
        for (int k = 0; k < KNB; k++){
            float v = simv[r]; int idx = t;
            #pragma unroll
            for (int off = 16; off; off >>= 1){
                float ov = __shfl_down_sync(0xffffffffu, v, off);
                int   oi = __shfl_down_sync(0xffffffffu, idx, off);
                if (ov > v || (ov == v && oi < idx)){ v = ov; idx = oi; }
            }
            if (lane == 0){ wv[warp] = v; wi[warp] = idx; }
            __syncthreads();
            if (warp == 0){
                float v2 = (lane < 8) ? wv[lane] : NEG_INF;
                int   i2 = (lane < 8) ? wi[lane] : 0x7fffffff;
                #pragma unroll
                for (int off = 4; off; off >>= 1){
                    float ov = __shfl_down_sync(0xffffffffu, v2, off);
                    int   oi = __shfl_down_sync(0xffffffffu, i2, off);
                    if (ov > v2 || (ov == v2 && oi < i2)){ v2 = ov; i2 = oi; }
                }
                if (lane == 0) bidx[r * KNB + k] = i2;
            }
            __syncthreads();
            if (t == bidx[r * KNB + k]) simv[r] = NEG_INF;
        }
    }
    const float* featb = (f == 0 ? f1 : f2) + b * N * D;
    if (t < D){
        #pragma unroll
        for (int r = 0; r < 4; r++){
            int i = i0 + r;
            int k0 = bidx[r * KNB], k1 = bidx[r * KNB + 1], k2 = bidx[r * KNB + 2];
            float n0 = featb[k0 * D + t], n1 = featb[k1 * D + t], n2 = featb[k2 * D + t];
            g_A[f][b][i][t] = featb[i * D + t] + 0.5f * ((n0 + n1 + n2) * (1.f / 3.f));
        }
    }
    if (t < 4){
        #pragma unroll
        for (int k = 0; k < KNB; k++)
            g_Idx[f][b][i0 + t][k] = bidx[t * KNB + k];
    }
}

// ---------------- phase A: raw-cls b=0 (512) || proj (256) || wprep (64) ----------------
__global__ void __launch_bounds__(256, 2) phaseA(
    const float* __restrict__ f1,  const float* __restrict__ f2,
    const float* __restrict__ sw0, const float* __restrict__ cw0,
    const float* __restrict__ cb0,
    const float* __restrict__ cg,  const float* __restrict__ cbe,
    const float* __restrict__ cm,  const float* __restrict__ cv,
    const float* __restrict__ cw1, const float* __restrict__ cb1)
{
    extern __shared__ char smb[];
    int bid = blockIdx.x;
    if (bid < 512){
        int j0 = (bid & 31) * 8, i0 = ((bid >> 5) & 15) * 16;
        cls_tile<true>(f1, f2, i0, j0, &g_S[1][0][0][0],
                       cw0, cb0, cg, cbe, cm, cv, cw1, cb1, smb);
    } else if (bid < 768){
        proj_part(bid - 512, f1, f2, sw0, smb);
    } else {
        int e = (bid - 768) * 256 + threadIdx.x;    // 64 blocks x 256 = 16384
        int d = e >> 7, k = e & 127;
        g_Wh[d * D + k] = __float2half_rn(cw0[k * D + d]);
    }
}

// ---------------- phase B: raw-cls b=1 (512) || topk (256) ----------------
__global__ void __launch_bounds__(256, 2) phaseB(
    const float* __restrict__ f1,  const float* __restrict__ f2,
    const float* __restrict__ sb0, const float* __restrict__ sg,
    const float* __restrict__ sbe, const float* __restrict__ smn,
    const float* __restrict__ sv,  const float* __restrict__ sw1,
    const float* __restrict__ cb0,
    const float* __restrict__ cg,  const float* __restrict__ cbe,
    const float* __restrict__ cm,  const float* __restrict__ cv,
    const float* __restrict__ cw1, const float* __restrict__ cb1)
{
    extern __shared__ char smb[];
    int bid = blockIdx.x;
    if (bid < 512){
        int j0 = (bid & 31) * 8, i0 = ((bid >> 5) & 15) * 16;
        cls_tile<false>(f1 + N * D, f2 + N * D, i0, j0, &g_S[1][1][0][0],
                        nullptr, cb0, cg, cbe, cm, cv, cw1, cb1, smb);
    } else {
        topk_part(bid - 512, f1, f2, sb0, sg, sbe, smn, sv, sw1, smb);
    }
}

// ---------------- phase C: anchor-cls (32 x 16 x 2) ----------------
__global__ void __launch_bounds__(256, 2) phaseC(
    const float* __restrict__ cb0,
    const float* __restrict__ cg,  const float* __restrict__ cbe,
    const float* __restrict__ cm,  const float* __restrict__ cv,
    const float* __restrict__ cw1, const float* __restrict__ cb1)
{
    extern __shared__ char smb[];
    int b = blockIdx.z;
    int i0 = blockIdx.y * 16, j0 = blockIdx.x * 8;
    cls_tile<false>(&g_A[0][b][0][0], &g_A[1][b][0][0], i0, j0, &g_S[0][b][0][0],
                    nullptr, cb0, cg, cbe, cm, cv, cw1, cb1, smb);
}

// ---------------- K4: combine anchor + gathered neighbor scores ----------------
__global__ void combine_kernel(float* __restrict__ out){
    int blk = blockIdx.x;             // 512 = b*256 + i
    int b = blk >> 8, i = blk & 255;
    int j = threadIdx.x;
    __shared__ int ia[KNB];
    if (j < KNB) ia[j] = g_Idx[0][b][i][j];
    __syncthreads();
    float sa = g_S[0][b][i][j];
    const int* bj = &g_Idx[1][b][j][0];
    int b0 = bj[0], b1 = bj[1], b2 = bj[2];
    float s = g_S[1][b][ia[0]][b0] + g_S[1][b][ia[1]][b1] + g_S[1][b][ia[2]][b2];
    out[(b * N + i) * N + j] = 0.5f * sa + (1.f / 6.f) * s;
}

// ---------------- launch ----------------
extern "C" void kernel_launch(void* const* d_in, const int* in_sizes, int n_in,
                              void* d_out, int out_size){
    const float* f1  = (const float*)d_in[0];
    const float* f2  = (const float*)d_in[1];
    const float* sw0 = (const float*)d_in[2];
    const float* sb0 = (const float*)d_in[3];
    const float* sg  = (const float*)d_in[4];
    const float* sbe = (const float*)d_in[5];
    const float* smn = (const float*)d_in[6];
    const float* sv  = (const float*)d_in[7];
    const float* sw1 = (const float*)d_in[8];
    /* d_in[9] = sim_b1: rank-invariant, unused */
    const float* cw0 = (const float*)d_in[10];
    const float* cb0 = (const float*)d_in[11];
    const float* cg  = (const float*)d_in[12];
    const float* cbe = (const float*)d_in[13];
    const float* cm  = (const float*)d_in[14];
    const float* cv  = (const float*)d_in[15];
    const float* cw1 = (const float*)d_in[16];
    const float* cb1 = (const float*)d_in[17];
    float* out = (float*)d_out;

    cudaFuncSetAttribute(phaseA, cudaFuncAttributeMaxDynamicSharedMemorySize, SMEM_BYTES);
    cudaFuncSetAttribute(phaseB, cudaFuncAttributeMaxDynamicSharedMemorySize, SMEM_BYTES);
    cudaFuncSetAttribute(phaseC, cudaFuncAttributeMaxDynamicSharedMemorySize, SMEM_BYTES);

    phaseA<<<832, 256, SMEM_BYTES>>>(f1, f2, sw0, cw0, cb0, cg, cbe, cm, cv, cw1, cb1);
    phaseB<<<768, 256, SMEM_BYTES>>>(f1, f2, sb0, sg, sbe, smn, sv, sw1,
                                     cb0, cg, cbe, cm, cv, cw1, cb1);
    dim3 gridC(32, 16, 2);
    phaseC<<<gridC, 256, SMEM_BYTES>>>(cb0, cg, cbe, cm, cv, cw1, cb1);
    combine_kernel<<<512, 256>>>(out);
}

// round 12
// speedup vs baseline: 1.0188x; 1.0188x over previous
#include <cuda_runtime.h>
#include <cuda_fp16.h>
#include <cstdint>
#include <math.h>

#define D   128
#define N   256
#define BSZ 2
#define KNB 3
#define EPSF 1e-5f
#define NEG_INF (-3.402823466e38f)

// ---------------- scratch (no allocs allowed) ----------------
__device__ float g_P [2][BSZ][N][D];
__device__ float g_Q [2][BSZ][N][D];
__device__ float g_A [2][BSZ][N][D];
__device__ int   g_Idx[2][BSZ][N][KNB];
__device__ float g_S [2][BSZ][N][N];   // [0]=anchor sigmoid, [1]=raw-pair sigmoid
__device__ __half g_Wh[D * D];         // W0^T as fp16: g_Wh[d*128 + k] = cw0[k*128 + d]

// ---------------- mma.sync / ldmatrix helpers (fp16, m16n8k16) ----------------
__device__ __forceinline__ void mma16(float c[4], const uint32_t a[4],
                                      uint32_t b0, uint32_t b1){
    asm volatile(
        "mma.sync.aligned.m16n8k16.row.col.f32.f16.f16.f32 "
        "{%0,%1,%2,%3}, {%4,%5,%6,%7}, {%8,%9}, {%0,%1,%2,%3};\n"
        : "+f"(c[0]), "+f"(c[1]), "+f"(c[2]), "+f"(c[3])
        : "r"(a[0]), "r"(a[1]), "r"(a[2]), "r"(a[3]), "r"(b0), "r"(b1));
}

__device__ __forceinline__ void ldm4(uint32_t r[4], uint32_t addr){
    asm volatile("ldmatrix.sync.aligned.m8n8.x4.shared.b16 {%0,%1,%2,%3}, [%4];"
        : "=r"(r[0]), "=r"(r[1]), "=r"(r[2]), "=r"(r[3]) : "r"(addr));
}

__device__ __forceinline__ uint32_t ad2(uint32_t a, uint32_t b){
    __half2 ha = *reinterpret_cast<__half2*>(&a);
    __half2 hb = *reinterpret_cast<__half2*>(&b);
    __half2 r  = __habs2(__hsub2(ha, hb));
    return *reinterpret_cast<uint32_t*>(&r);
}

// butterfly argmax (greater, tie -> lower index); all lanes converge
__device__ __forceinline__ void warp_amax(float& v, int& idx){
    #pragma unroll
    for (int off = 16; off; off >>= 1){
        float ov = __shfl_xor_sync(0xffffffffu, v, off);
        int   oi = __shfl_xor_sync(0xffffffffu, idx, off);
        if (ov > v || (ov == v && oi < idx)){ v = ov; idx = oi; }
    }
}

// ---------------- K1: P/Q projections (blocks 0..511) + W0^T fp16 prep (blocks 512..639) ----------------
__global__ void proj_kernel(const float* __restrict__ f1, const float* __restrict__ f2,
                            const float* __restrict__ sw0, const float* __restrict__ cw0){
    if (blockIdx.x >= 512){
        int e = (blockIdx.x - 512) * 128 + threadIdx.x;   // 128 blocks x 128 = 16384
        int d = e >> 7, k = e & 127;
        g_Wh[d * D + k] = __float2half_rn(cw0[k * D + d]);
        return;
    }
    __shared__ float fs[4][D];
    int which = blockIdx.x >> 8;
    int grp = blockIdx.x & 255;
    int f = grp >> 7, b = (grp >> 6) & 1, i0 = (grp & 63) * 4;
    const float* featb = (f == 0 ? f1 : f2) + b * N * D;
    int d = threadIdx.x;                      // 128 threads
    for (int e = d; e < 4 * D; e += 128){
        int r = e >> 7, c = e & 127;
        fs[r][c] = featb[(i0 + r) * D + c];
    }
    __syncthreads();
    const float* wb = sw0 + which * D * D + d;
    float a0 = 0.f, a1 = 0.f, a2 = 0.f, a3 = 0.f;
    #pragma unroll 8
    for (int c = 0; c < D; c++){
        float w = wb[c * D];
        a0 = fmaf(fs[0][c], w, a0);
        a1 = fmaf(fs[1][c], w, a1);
        a2 = fmaf(fs[2][c], w, a2);
        a3 = fmaf(fs[3][c], w, a3);
    }
    float* dst = which ? &g_Q[f][b][0][0] : &g_P[f][b][0][0];
    dst[(i0    ) * D + d] = a0;
    dst[(i0 + 1) * D + d] = a1;
    dst[(i0 + 2) * D + d] = a2;
    dst[(i0 + 3) * D + d] = a3;
}

// ---------------- K2: 4 i's per block: sim rows -> top3 (2 syncs total) -> absorb + indices ----------------
__global__ void topk_kernel(const float* __restrict__ f1, const float* __restrict__ f2,
        const float* __restrict__ sb0, const float* __restrict__ sg,
        const float* __restrict__ sbe, const float* __restrict__ smn,
        const float* __restrict__ sv,  const float* __restrict__ sw1){
    int gb = blockIdx.x;                       // 256 blocks
    int f = gb >> 7, b = (gb >> 6) & 1, i0 = (gb & 63) * 4;
    __shared__ float Ps[4][D], ss[D], tt[D], w1s[D];
    __shared__ float cv_[4][8][KNB];           // per-row per-warp top-3 values
    __shared__ int   ci_[4][8][KNB];
    __shared__ int   bidx[4][KNB];
    int t = threadIdx.x, lane = t & 31, warp = t >> 5;
    if (t < D){
        float s = sg[t] * rsqrtf(sv[t] + EPSF);
        ss[t]  = s;
        tt[t]  = (sb0[t] - smn[t]) * s + sbe[t];
        w1s[t] = sw1[t];
        #pragma unroll
        for (int r = 0; r < 4; r++) Ps[r][t] = g_P[f][b][i0 + r][t];
    }
    __syncthreads();
    const float* Qrow = &g_Q[f][b][t][0];
    float simv[4] = {0.f, 0.f, 0.f, 0.f};
    #pragma unroll 4
    for (int d = 0; d < D; d += 4){
        float4 q = *(const float4*)(Qrow + d);
        float s0 = ss[d], s1 = ss[d+1], s2 = ss[d+2], s3 = ss[d+3];
        float t0 = tt[d], t1 = tt[d+1], t2 = tt[d+2], t3 = tt[d+3];
        float w0 = w1s[d], w1 = w1s[d+1], w2 = w1s[d+2], w3 = w1s[d+3];
        #pragma unroll
        for (int r = 0; r < 4; r++){
            float h0 = (Ps[r][d]   + q.x) * s0 + t0;
            float h1 = (Ps[r][d+1] + q.y) * s1 + t1;
            float h2 = (Ps[r][d+2] + q.z) * s2 + t2;
            float h3 = (Ps[r][d+3] + q.w) * s3 + t3;
            simv[r] += fmaxf(h0, 0.f) * w0 + fmaxf(h1, 0.f) * w1
                     + fmaxf(h2, 0.f) * w2 + fmaxf(h3, 0.f) * w3;
        }
    }
    #pragma unroll
    for (int r = 0; r < 4; r++) if (t == i0 + r) simv[r] = NEG_INF;   // exclude self

    // per-warp top-3 per row (no block syncs)
    #pragma unroll
    for (int r = 0; r < 4; r++){
        float v = simv[r];
        #pragma unroll
        for (int k = 0; k < KNB; k++){
            float mv = v; int mi = t;
            warp_amax(mv, mi);
            if (lane == 0){ cv_[r][warp][k] = mv; ci_[r][warp][k] = mi; }
            if (t == mi) v = NEG_INF;          // warp-local invalidate
        }
    }
    __syncthreads();
    // warp 0: reduce 24 candidates per row to global top-3
    if (warp == 0){
        #pragma unroll
        for (int r = 0; r < 4; r++){
            float v = (lane < 24) ? cv_[r][lane / KNB][lane % KNB] : NEG_INF;
            int idx = (lane < 24) ? ci_[r][lane / KNB][lane % KNB] : 0x7fffffff;
            #pragma unroll
            for (int k = 0; k < KNB; k++){
                float mv = v; int mi = idx;
                warp_amax(mv, mi);
                if (lane == 0) bidx[r][k] = mi;
                if (idx == mi) v = NEG_INF;
            }
        }
    }
    __syncthreads();
    const float* featb = (f == 0 ? f1 : f2) + b * N * D;
    if (t < D){
        #pragma unroll
        for (int r = 0; r < 4; r++){
            int i = i0 + r;
            int k0 = bidx[r][0], k1 = bidx[r][1], k2 = bidx[r][2];
            float n0 = featb[k0 * D + t], n1 = featb[k1 * D + t], n2 = featb[k2 * D + t];
            g_A[f][b][i][t] = featb[i * D + t] + 0.5f * ((n0 + n1 + n2) * (1.f / 3.f));
        }
    }
    if (t < 4){
        #pragma unroll
        for (int k = 0; k < KNB; k++)
            g_Idx[f][b][i0 + t][k] = bidx[t][k];
    }
}

// ---------------- K3: pair-sigmoid GEMM, ONE channel per block, 128-pair tiles ----------------
// XOR-swizzled smem: logical (row, chunk[16B]) -> phys row*256 + (chunk ^ (row&7))*16
#define OFF_PS   0
#define OFF_PT   512
#define OFF_PW   1024
#define OFF_LG   1536     // 128 floats
#define OFF_US   2048     // Ush2: 16 x 68 uint32 = 4352
#define OFF_VS   6400     // Vsh2:  8 x 68 uint32 = 2176
#define OFF_WT   8704     // Wt swizzled fp16 [128 d][128 k] = 32768
#define OFF_XS   41472    // Xs swizzled fp16 [128 pair][128 k] = 32768
#define SMEM_BYTES 74240
#define UPAD 68

__global__ void __launch_bounds__(256, 2) cls_kernel(
    const float* __restrict__ f1,  const float* __restrict__ f2,
    const float* __restrict__ cb0,
    const float* __restrict__ cg,  const float* __restrict__ cbe,
    const float* __restrict__ cm,  const float* __restrict__ cv,
    const float* __restrict__ cw1, const float* __restrict__ cb1)
{
    extern __shared__ char smb[];
    float*    ps    = (float*)   (smb + OFF_PS);
    float*    pt    = (float*)   (smb + OFF_PT);
    float*    pw1   = (float*)   (smb + OFF_PW);
    float*    logit = (float*)   (smb + OFF_LG);
    uint32_t* Ush2  = (uint32_t*)(smb + OFF_US);
    uint32_t* Vsh2  = (uint32_t*)(smb + OFF_VS);
    char*     Xs    = smb + OFF_XS;
    uint32_t smem_base = (uint32_t)__cvta_generic_to_shared(smb);
    uint32_t wt_s = smem_base + OFF_WT;
    uint32_t xs_s = smem_base + OFF_XS;

    int t = threadIdx.x;
    int bz = blockIdx.z;                       // 4 = b*2 + ch
    int b = bz >> 1, ch = bz & 1;
    int i0 = blockIdx.y * 16, j0 = blockIdx.x * 8;
    int lane = t & 31, warp = t >> 5;
    int gid = lane >> 2, tig = lane & 3;
    int pg = warp >> 1, dg = warp & 1;        // 4 pair-groups (32 pairs) x 2 d-groups (64 d)

    const float* Ubase = (ch == 0) ? &g_A[0][b][0][0] : (f1 + b * N * D);
    const float* Vbase = (ch == 0) ? &g_A[1][b][0][0] : (f2 + b * N * D);

    // stage swizzled Wt from prepped fp16 (8 x LDG.128/STS.128 per thread)
    #pragma unroll
    for (int i = 0; i < 8; i++){
        int e = t + i * 256;                  // 2048 16B chunks
        int d = e >> 4, ck = e & 15;
        uint4 v = *(const uint4*)(g_Wh + d * D + ck * 8);
        *(uint4*)(smb + OFF_WT + d * 256 + ((ck ^ (d & 7)) << 4)) = v;
    }
    if (t < D){
        float s = cg[t] * rsqrtf(cv[t] + EPSF);
        ps[t]  = s;
        pt[t]  = (cb0[t] - cm[t]) * s + cbe[t];
        pw1[t] = cw1[t];
    }
    if (t < 128) logit[t] = cb1[0];
    // stage U (16 rows) / V (8 rows) as half2 (coalesced float2 LDG)
    for (int e = t; e < 16 * 64; e += 256){
        int r = e >> 6, c = e & 63;
        float2 fu = *(const float2*)(Ubase + (i0 + r) * D + 2 * c);
        __half2 hu = __floats2half2_rn(fu.x, fu.y);
        Ush2[r * UPAD + c] = *(uint32_t*)&hu;
    }
    for (int e = t; e < 8 * 64; e += 256){
        int r = e >> 6, c = e & 63;
        float2 fv = *(const float2*)(Vbase + (j0 + r) * D + 2 * c);
        __half2 hv = __floats2half2_rn(fv.x, fv.y);
        Vsh2[r * UPAD + c] = *(uint32_t*)&hv;
    }
    __syncthreads();

    // build X = |U_i - V_j| into swizzled tile: 8 STS.128 per thread
    {
        int g2 = t >> 4, kO = t & 15;
        int ib = (g2 >> 1) * 2;
        int jb = (g2 & 1) * 4;
        uint4 u0 = *(const uint4*)(Ush2 +  ib      * UPAD + kO * 4);
        uint4 u1 = *(const uint4*)(Ush2 + (ib + 1) * UPAD + kO * 4);
        #pragma unroll
        for (int jj = 0; jj < 4; jj++){
            uint4 v = *(const uint4*)(Vsh2 + (jb + jj) * UPAD + kO * 4);
            uint4 x0, x1;
            x0.x = ad2(u0.x, v.x); x0.y = ad2(u0.y, v.y);
            x0.z = ad2(u0.z, v.z); x0.w = ad2(u0.w, v.w);
            x1.x = ad2(u1.x, v.x); x1.y = ad2(u1.y, v.y);
            x1.z = ad2(u1.z, v.z); x1.w = ad2(u1.w, v.w);
            int p0 =  ib      * 8 + jb + jj;
            int p1 = (ib + 1) * 8 + jb + jj;
            *(uint4*)(Xs + p0 * 256 + ((kO ^ (p0 & 7)) << 4)) = x0;
            *(uint4*)(Xs + p1 * 256 + ((kO ^ (p1 & 7)) << 4)) = x1;
        }
    }
    __syncthreads();

    // A (Xs) ldmatrix: two m-tiles (16 pairs each)
    int a_row0 = pg * 32 + (lane & 15);
    int a_row1 = a_row0 + 16;
    uint32_t a0_base = xs_s + a_row0 * 256;
    uint32_t a1_base = xs_s + a_row1 * 256;
    int a0_r7 = a_row0 & 7, a_hi = lane >> 4;
    int a1_r7 = a_row1 & 7;
    // B (Wt)
    int b_row_off = (lane & 7) + (((lane >> 4) & 1) << 3);
    int b_khi = (lane >> 3) & 1;
    uint32_t bw_base[4]; int bw_r7[4];
    #pragma unroll
    for (int ng = 0; ng < 4; ng++){
        int row = dg * 64 + ng * 16 + b_row_off;
        bw_base[ng] = wt_s + row * 256;
        bw_r7[ng]   = row & 7;
    }

    float cacc[2][8][4];
    #pragma unroll
    for (int mt = 0; mt < 2; mt++)
        #pragma unroll
        for (int nt = 0; nt < 8; nt++)
            #pragma unroll
            for (int q = 0; q < 4; q++) cacc[mt][nt][q] = 0.f;

    #pragma unroll 2
    for (int ks = 0; ks < 8; ks++){
        int ck = 2 * ks;
        uint32_t aX0[4], aX1[4];
        ldm4(aX0, a0_base + (((ck + a_hi) ^ a0_r7) << 4));
        ldm4(aX1, a1_base + (((ck + a_hi) ^ a1_r7) << 4));
        #pragma unroll
        for (int ng = 0; ng < 4; ng++){
            uint32_t bW[4];
            ldm4(bW, bw_base[ng] + (((ck + b_khi) ^ bw_r7[ng]) << 4));
            mma16(cacc[0][ng * 2],     aX0, bW[0], bW[1]);
            mma16(cacc[0][ng * 2 + 1], aX0, bW[2], bW[3]);
            mma16(cacc[1][ng * 2],     aX1, bW[0], bW[1]);
            mma16(cacc[1][ng * 2 + 1], aX1, bW[2], bW[3]);
        }
    }

    // epilogue: rows = pairs, cols = d (this warp's 64-d half); reduce d in-thread
    #pragma unroll
    for (int mt = 0; mt < 2; mt++){
        float l0 = 0.f, l1 = 0.f;
        #pragma unroll
        for (int nt = 0; nt < 8; nt++){
            int d0 = dg * 64 + (nt >> 1) * 16 + (nt & 1) * 8 + 2 * tig;
            float s0 = ps[d0], t0 = pt[d0], w0 = pw1[d0];
            float s1 = ps[d0 + 1], t1 = pt[d0 + 1], w1 = pw1[d0 + 1];
            float* c = cacc[mt][nt];
            l0 += fmaxf(c[0] * s0 + t0, 0.f) * w0 + fmaxf(c[1] * s1 + t1, 0.f) * w1;
            l1 += fmaxf(c[2] * s0 + t0, 0.f) * w0 + fmaxf(c[3] * s1 + t1, 0.f) * w1;
        }
        l0 += __shfl_xor_sync(0xffffffffu, l0, 1);
        l0 += __shfl_xor_sync(0xffffffffu, l0, 2);
        l1 += __shfl_xor_sync(0xffffffffu, l1, 1);
        l1 += __shfl_xor_sync(0xffffffffu, l1, 2);
        if (tig == 0){
            atomicAdd(&logit[pg * 32 + mt * 16 + gid],     l0);
            atomicAdd(&logit[pg * 32 + mt * 16 + gid + 8], l1);
        }
    }
    __syncthreads();
    if (t < 128){
        float sc = 1.f / (1.f + expf(-logit[t]));
        g_S[ch][b][i0 + (t >> 3)][j0 + (t & 7)] = sc;
    }
}

// ---------------- K4: combine anchor + gathered neighbor scores (no syncs) ----------------
__global__ void combine_kernel(float* __restrict__ out){
    int blk = blockIdx.x;             // 512 = b*256 + i
    int b = blk >> 8, i = blk & 255;
    int j = threadIdx.x;
    // uniform-address loads broadcast from L1
    int ia0 = __ldg(&g_Idx[0][b][i][0]);
    int ia1 = __ldg(&g_Idx[0][b][i][1]);
    int ia2 = __ldg(&g_Idx[0][b][i][2]);
    float sa = g_S[0][b][i][j];
    const int* bj = &g_Idx[1][b][j][0];
    int b0 = bj[0], b1 = bj[1], b2 = bj[2];
    float s = g_S[1][b][ia0][b0] + g_S[1][b][ia1][b1] + g_S[1][b][ia2][b2];
    out[(b * N + i) * N + j] = 0.5f * sa + (1.f / 6.f) * s;
}

// ---------------- launch ----------------
extern "C" void kernel_launch(void* const* d_in, const int* in_sizes, int n_in,
                              void* d_out, int out_size){
    const float* f1  = (const float*)d_in[0];
    const float* f2  = (const float*)d_in[1];
    const float* sw0 = (const float*)d_in[2];
    const float* sb0 = (const float*)d_in[3];
    const float* sg  = (const float*)d_in[4];
    const float* sbe = (const float*)d_in[5];
    const float* smn = (const float*)d_in[6];
    const float* sv  = (const float*)d_in[7];
    const float* sw1 = (const float*)d_in[8];
    /* d_in[9] = sim_b1: rank-invariant, unused */
    const float* cw0 = (const float*)d_in[10];
    const float* cb0 = (const float*)d_in[11];
    const float* cg  = (const float*)d_in[12];
    const float* cbe = (const float*)d_in[13];
    const float* cm  = (const float*)d_in[14];
    const float* cv  = (const float*)d_in[15];
    const float* cw1 = (const float*)d_in[16];
    const float* cb1 = (const float*)d_in[17];
    float* out = (float*)d_out;

    cudaFuncSetAttribute(cls_kernel, cudaFuncAttributeMaxDynamicSharedMemorySize,
                         SMEM_BYTES);

    proj_kernel<<<640, 128>>>(f1, f2, sw0, cw0);
    topk_kernel<<<256, 256>>>(f1, f2, sb0, sg, sbe, smn, sv, sw1);
    dim3 grid(32, 16, 4);
    cls_kernel<<<grid, 256, SMEM_BYTES>>>(
        f1, f2, cb0, cg, cbe, cm, cv, cw1, cb1);
    combine_kernel<<<512, 256>>>(out);
}

// round 13
// speedup vs baseline: 1.0449x; 1.0256x over previous
#include <cuda_runtime.h>
#include <cuda_fp16.h>
#include <cstdint>
#include <math.h>

#define D   128
#define N   256
#define BSZ 2
#define KNB 3
#define EPSF 1e-5f
#define NEG_INF (-3.402823466e38f)

// ---------------- scratch (no allocs allowed) ----------------
__device__ float g_P [2][BSZ][N][D];
__device__ float g_Q [2][BSZ][N][D];
__device__ float g_A [2][BSZ][N][D];
__device__ int   g_Idx[2][BSZ][N][KNB];
__device__ float g_Sr[BSZ][N][N];      // raw-pair sigmoid
__device__ __half g_Wh[D * D];         // W0^T as fp16: g_Wh[d*128 + k] = cw0[k*128 + d]

// ---------------- mma.sync / ldmatrix helpers (fp16, m16n8k16) ----------------
__device__ __forceinline__ void mma16(float c[4], const uint32_t a[4],
                                      uint32_t b0, uint32_t b1){
    asm volatile(
        "mma.sync.aligned.m16n8k16.row.col.f32.f16.f16.f32 "
        "{%0,%1,%2,%3}, {%4,%5,%6,%7}, {%8,%9}, {%0,%1,%2,%3};\n"
        : "+f"(c[0]), "+f"(c[1]), "+f"(c[2]), "+f"(c[3])
        : "r"(a[0]), "r"(a[1]), "r"(a[2]), "r"(a[3]), "r"(b0), "r"(b1));
}

__device__ __forceinline__ void ldm4(uint32_t r[4], uint32_t addr){
    asm volatile("ldmatrix.sync.aligned.m8n8.x4.shared.b16 {%0,%1,%2,%3}, [%4];"
        : "=r"(r[0]), "=r"(r[1]), "=r"(r[2]), "=r"(r[3]) : "r"(addr));
}

__device__ __forceinline__ uint32_t ad2(uint32_t a, uint32_t b){
    __half2 ha = *reinterpret_cast<__half2*>(&a);
    __half2 hb = *reinterpret_cast<__half2*>(&b);
    __half2 r  = __habs2(__hsub2(ha, hb));
    return *reinterpret_cast<uint32_t*>(&r);
}

// butterfly argmax (greater, tie -> lower index); all lanes converge
__device__ __forceinline__ void warp_amax(float& v, int& idx){
    #pragma unroll
    for (int off = 16; off; off >>= 1){
        float ov = __shfl_xor_sync(0xffffffffu, v, off);
        int   oi = __shfl_xor_sync(0xffffffffu, idx, off);
        if (ov > v || (ov == v && oi < idx)){ v = ov; idx = oi; }
    }
}

// ---------------- K1: P/Q projections (512 blocks, c-split) + W prep (64 blocks) ----------------
__global__ void __launch_bounds__(256) proj_kernel(
        const float* __restrict__ f1, const float* __restrict__ f2,
        const float* __restrict__ sw0, const float* __restrict__ cw0){
    if (blockIdx.x >= 512){
        int e = (blockIdx.x - 512) * 256 + threadIdx.x;   // 64 blocks x 256 = 16384
        int d = e >> 7, k = e & 127;
        g_Wh[d * D + k] = __float2half_rn(cw0[k * D + d]);
        return;
    }
    __shared__ float fs[4][D];
    __shared__ float part[4][D];
    int which = blockIdx.x >> 8;              // 0 -> P, 1 -> Q
    int grp = blockIdx.x & 255;
    int f = grp >> 7, b = (grp >> 6) & 1, i0 = (grp & 63) * 4;
    const float* featb = (f == 0 ? f1 : f2) + b * N * D;
    int t = threadIdx.x;
    int d = t & 127, h = t >> 7;              // h = c-half
    for (int e = t; e < 4 * D; e += 256){
        int r = e >> 7, c = e & 127;
        fs[r][c] = featb[(i0 + r) * D + c];
    }
    __syncthreads();
    const float* wb = sw0 + which * D * D + d;
    int c0 = h * 64;
    float a0 = 0.f, a1 = 0.f, a2 = 0.f, a3 = 0.f;
    #pragma unroll 8
    for (int c = c0; c < c0 + 64; c++){
        float w = wb[c * D];
        a0 = fmaf(fs[0][c], w, a0);
        a1 = fmaf(fs[1][c], w, a1);
        a2 = fmaf(fs[2][c], w, a2);
        a3 = fmaf(fs[3][c], w, a3);
    }
    if (h == 1){
        part[0][d] = a0; part[1][d] = a1; part[2][d] = a2; part[3][d] = a3;
    }
    __syncthreads();
    if (h == 0){
        float* dst = which ? &g_Q[f][b][0][0] : &g_P[f][b][0][0];
        dst[(i0    ) * D + d] = a0 + part[0][d];
        dst[(i0 + 1) * D + d] = a1 + part[1][d];
        dst[(i0 + 2) * D + d] = a2 + part[2][d];
        dst[(i0 + 3) * D + d] = a3 + part[3][d];
    }
}

// ---------------- K2: 4 i's per block: sim rows -> top3 (2 syncs) -> absorb + indices ----------------
__global__ void topk_kernel(const float* __restrict__ f1, const float* __restrict__ f2,
        const float* __restrict__ sb0, const float* __restrict__ sg,
        const float* __restrict__ sbe, const float* __restrict__ smn,
        const float* __restrict__ sv,  const float* __restrict__ sw1){
    int gb = blockIdx.x;                       // 256 blocks
    int f = gb >> 7, b = (gb >> 6) & 1, i0 = (gb & 63) * 4;
    __shared__ float Ps[4][D], ss[D], tt[D], w1s[D];
    __shared__ float cv_[4][8][KNB];
    __shared__ int   ci_[4][8][KNB];
    __shared__ int   bidx[4][KNB];
    int t = threadIdx.x, lane = t & 31, warp = t >> 5;
    if (t < D){
        float s = sg[t] * rsqrtf(sv[t] + EPSF);
        ss[t]  = s;
        tt[t]  = (sb0[t] - smn[t]) * s + sbe[t];
        w1s[t] = sw1[t];
        #pragma unroll
        for (int r = 0; r < 4; r++) Ps[r][t] = g_P[f][b][i0 + r][t];
    }
    __syncthreads();
    const float* Qrow = &g_Q[f][b][t][0];
    float simv[4] = {0.f, 0.f, 0.f, 0.f};
    #pragma unroll 4
    for (int d = 0; d < D; d += 4){
        float4 q = *(const float4*)(Qrow + d);
        float s0 = ss[d], s1 = ss[d+1], s2 = ss[d+2], s3 = ss[d+3];
        float t0 = tt[d], t1 = tt[d+1], t2 = tt[d+2], t3 = tt[d+3];
        float w0 = w1s[d], w1 = w1s[d+1], w2 = w1s[d+2], w3 = w1s[d+3];
        #pragma unroll
        for (int r = 0; r < 4; r++){
            float h0 = (Ps[r][d]   + q.x) * s0 + t0;
            float h1 = (Ps[r][d+1] + q.y) * s1 + t1;
            float h2 = (Ps[r][d+2] + q.z) * s2 + t2;
            float h3 = (Ps[r][d+3] + q.w) * s3 + t3;
            simv[r] += fmaxf(h0, 0.f) * w0 + fmaxf(h1, 0.f) * w1
                     + fmaxf(h2, 0.f) * w2 + fmaxf(h3, 0.f) * w3;
        }
    }
    #pragma unroll
    for (int r = 0; r < 4; r++) if (t == i0 + r) simv[r] = NEG_INF;   // exclude self

    #pragma unroll
    for (int r = 0; r < 4; r++){
        float v = simv[r];
        #pragma unroll
        for (int k = 0; k < KNB; k++){
            float mv = v; int mi = t;
            warp_amax(mv, mi);
            if (lane == 0){ cv_[r][warp][k] = mv; ci_[r][warp][k] = mi; }
            if (t == mi) v = NEG_INF;
        }
    }
    __syncthreads();
    if (warp == 0){
        #pragma unroll
        for (int r = 0; r < 4; r++){
            float v = (lane < 24) ? cv_[r][lane / KNB][lane % KNB] : NEG_INF;
            int idx = (lane < 24) ? ci_[r][lane / KNB][lane % KNB] : 0x7fffffff;
            #pragma unroll
            for (int k = 0; k < KNB; k++){
                float mv = v; int mi = idx;
                warp_amax(mv, mi);
                if (lane == 0) bidx[r][k] = mi;
                if (idx == mi) v = NEG_INF;
            }
        }
    }
    __syncthreads();
    const float* featb = (f == 0 ? f1 : f2) + b * N * D;
    if (t < D){
        #pragma unroll
        for (int r = 0; r < 4; r++){
            int i = i0 + r;
            int k0 = bidx[r][0], k1 = bidx[r][1], k2 = bidx[r][2];
            float n0 = featb[k0 * D + t], n1 = featb[k1 * D + t], n2 = featb[k2 * D + t];
            g_A[f][b][i][t] = featb[i * D + t] + 0.5f * ((n0 + n1 + n2) * (1.f / 3.f));
        }
    }
    if (t < 4){
        #pragma unroll
        for (int k = 0; k < KNB; k++)
            g_Idx[f][b][i0 + t][k] = bidx[t][k];
    }
}

// ---------------- cls tile core (shared by raw/anchor) ----------------
// XOR-swizzled smem: logical (row, chunk[16B]) -> phys row*256 + (chunk ^ (row&7))*16
#define OFF_PS   0
#define OFF_PT   512
#define OFF_PW   1024
#define OFF_LG   1536     // 128 floats
#define OFF_US   2048     // Ush2: 16 x 68 uint32 = 4352
#define OFF_VS   6400     // Vsh2:  8 x 68 uint32 = 2176
#define OFF_WT   8704     // Wt swizzled fp16 [128 d][128 k] = 32768
#define OFF_XS   41472    // Xs swizzled fp16 [128 pair][128 k] = 32768
#define SMEM_BYTES 74240
#define UPAD 68

__device__ __forceinline__ void cls_core(
    const float* __restrict__ Ubase, const float* __restrict__ Vbase,
    int i0, int j0,
    const float* __restrict__ cb0, const float* __restrict__ cg,
    const float* __restrict__ cbe, const float* __restrict__ cm,
    const float* __restrict__ cv,  const float* __restrict__ cw1,
    const float* __restrict__ cb1, char* smb)
{
    float*    ps    = (float*)   (smb + OFF_PS);
    float*    pt    = (float*)   (smb + OFF_PT);
    float*    pw1   = (float*)   (smb + OFF_PW);
    float*    logit = (float*)   (smb + OFF_LG);
    uint32_t* Ush2  = (uint32_t*)(smb + OFF_US);
    uint32_t* Vsh2  = (uint32_t*)(smb + OFF_VS);
    char*     Xs    = smb + OFF_XS;
    uint32_t smem_base = (uint32_t)__cvta_generic_to_shared(smb);
    uint32_t wt_s = smem_base + OFF_WT;
    uint32_t xs_s = smem_base + OFF_XS;

    int t = threadIdx.x;
    int lane = t & 31, warp = t >> 5;
    int gid = lane >> 2, tig = lane & 3;
    int pg = warp >> 1, dg = warp & 1;        // 4 pair-groups (32 pairs) x 2 d-groups (64 d)

    // stage swizzled Wt from prepped fp16 (8 x LDG.128/STS.128 per thread)
    #pragma unroll
    for (int i = 0; i < 8; i++){
        int e = t + i * 256;                  // 2048 16B chunks
        int d = e >> 4, ck = e & 15;
        uint4 v = *(const uint4*)(g_Wh + d * D + ck * 8);
        *(uint4*)(smb + OFF_WT + d * 256 + ((ck ^ (d & 7)) << 4)) = v;
    }
    if (t < D){
        float s = cg[t] * rsqrtf(cv[t] + EPSF);
        ps[t]  = s;
        pt[t]  = (cb0[t] - cm[t]) * s + cbe[t];
        pw1[t] = cw1[t];
    }
    if (t < 128) logit[t] = cb1[0];
    // stage U (16 rows) / V (8 rows) as half2 (coalesced float2 LDG)
    for (int e = t; e < 16 * 64; e += 256){
        int r = e >> 6, c = e & 63;
        float2 fu = *(const float2*)(Ubase + (i0 + r) * D + 2 * c);
        __half2 hu = __floats2half2_rn(fu.x, fu.y);
        Ush2[r * UPAD + c] = *(uint32_t*)&hu;
    }
    for (int e = t; e < 8 * 64; e += 256){
        int r = e >> 6, c = e & 63;
        float2 fv = *(const float2*)(Vbase + (j0 + r) * D + 2 * c);
        __half2 hv = __floats2half2_rn(fv.x, fv.y);
        Vsh2[r * UPAD + c] = *(uint32_t*)&hv;
    }
    __syncthreads();

    // build X = |U_i - V_j| into swizzled tile: 8 STS.128 per thread
    {
        int g2 = t >> 4, kO = t & 15;
        int ib = (g2 >> 1) * 2;
        int jb = (g2 & 1) * 4;
        uint4 u0 = *(const uint4*)(Ush2 +  ib      * UPAD + kO * 4);
        uint4 u1 = *(const uint4*)(Ush2 + (ib + 1) * UPAD + kO * 4);
        #pragma unroll
        for (int jj = 0; jj < 4; jj++){
            uint4 v = *(const uint4*)(Vsh2 + (jb + jj) * UPAD + kO * 4);
            uint4 x0, x1;
            x0.x = ad2(u0.x, v.x); x0.y = ad2(u0.y, v.y);
            x0.z = ad2(u0.z, v.z); x0.w = ad2(u0.w, v.w);
            x1.x = ad2(u1.x, v.x); x1.y = ad2(u1.y, v.y);
            x1.z = ad2(u1.z, v.z); x1.w = ad2(u1.w, v.w);
            int p0 =  ib      * 8 + jb + jj;
            int p1 = (ib + 1) * 8 + jb + jj;
            *(uint4*)(Xs + p0 * 256 + ((kO ^ (p0 & 7)) << 4)) = x0;
            *(uint4*)(Xs + p1 * 256 + ((kO ^ (p1 & 7)) << 4)) = x1;
        }
    }
    __syncthreads();

    // A (Xs) ldmatrix: two m-tiles (16 pairs each)
    int a_row0 = pg * 32 + (lane & 15);
    int a_row1 = a_row0 + 16;
    uint32_t a0_base = xs_s + a_row0 * 256;
    uint32_t a1_base = xs_s + a_row1 * 256;
    int a0_r7 = a_row0 & 7, a_hi = lane >> 4;
    int a1_r7 = a_row1 & 7;
    int b_row_off = (lane & 7) + (((lane >> 4) & 1) << 3);
    int b_khi = (lane >> 3) & 1;
    uint32_t bw_base[4]; int bw_r7[4];
    #pragma unroll
    for (int ng = 0; ng < 4; ng++){
        int row = dg * 64 + ng * 16 + b_row_off;
        bw_base[ng] = wt_s + row * 256;
        bw_r7[ng]   = row & 7;
    }

    float cacc[2][8][4];
    #pragma unroll
    for (int mt = 0; mt < 2; mt++)
        #pragma unroll
        for (int nt = 0; nt < 8; nt++)
            #pragma unroll
            for (int q = 0; q < 4; q++) cacc[mt][nt][q] = 0.f;

    #pragma unroll 2
    for (int ks = 0; ks < 8; ks++){
        int ck = 2 * ks;
        uint32_t aX0[4], aX1[4];
        ldm4(aX0, a0_base + (((ck + a_hi) ^ a0_r7) << 4));
        ldm4(aX1, a1_base + (((ck + a_hi) ^ a1_r7) << 4));
        #pragma unroll
        for (int ng = 0; ng < 4; ng++){
            uint32_t bW[4];
            ldm4(bW, bw_base[ng] + (((ck + b_khi) ^ bw_r7[ng]) << 4));
            mma16(cacc[0][ng * 2],     aX0, bW[0], bW[1]);
            mma16(cacc[0][ng * 2 + 1], aX0, bW[2], bW[3]);
            mma16(cacc[1][ng * 2],     aX1, bW[0], bW[1]);
            mma16(cacc[1][ng * 2 + 1], aX1, bW[2], bW[3]);
        }
    }

    // epilogue: reduce d in-thread, accumulate into logit
    #pragma unroll
    for (int mt = 0; mt < 2; mt++){
        float l0 = 0.f, l1 = 0.f;
        #pragma unroll
        for (int nt = 0; nt < 8; nt++){
            int d0 = dg * 64 + (nt >> 1) * 16 + (nt & 1) * 8 + 2 * tig;
            float s0 = ps[d0], t0 = pt[d0], w0 = pw1[d0];
            float s1 = ps[d0 + 1], t1 = pt[d0 + 1], w1 = pw1[d0 + 1];
            float* c = cacc[mt][nt];
            l0 += fmaxf(c[0] * s0 + t0, 0.f) * w0 + fmaxf(c[1] * s1 + t1, 0.f) * w1;
            l1 += fmaxf(c[2] * s0 + t0, 0.f) * w0 + fmaxf(c[3] * s1 + t1, 0.f) * w1;
        }
        l0 += __shfl_xor_sync(0xffffffffu, l0, 1);
        l0 += __shfl_xor_sync(0xffffffffu, l0, 2);
        l1 += __shfl_xor_sync(0xffffffffu, l1, 1);
        l1 += __shfl_xor_sync(0xffffffffu, l1, 2);
        if (tig == 0){
            atomicAdd(&logit[pg * 32 + mt * 16 + gid],     l0);
            atomicAdd(&logit[pg * 32 + mt * 16 + gid + 8], l1);
        }
    }
    __syncthreads();
}

// ---------------- K3a: raw-pair GEMM -> g_Sr ----------------
__global__ void __launch_bounds__(256, 2) raw_cls(
    const float* __restrict__ f1,  const float* __restrict__ f2,
    const float* __restrict__ cb0,
    const float* __restrict__ cg,  const float* __restrict__ cbe,
    const float* __restrict__ cm,  const float* __restrict__ cv,
    const float* __restrict__ cw1, const float* __restrict__ cb1)
{
    extern __shared__ char smb[];
    int b = blockIdx.z;
    int i0 = blockIdx.y * 16, j0 = blockIdx.x * 8;
    cls_core(f1 + b * N * D, f2 + b * N * D, i0, j0,
             cb0, cg, cbe, cm, cv, cw1, cb1, smb);
    float* logit = (float*)(smb + OFF_LG);
    int t = threadIdx.x;
    if (t < 128){
        float sc = 1.f / (1.f + expf(-logit[t]));
        g_Sr[b][i0 + (t >> 3)][j0 + (t & 7)] = sc;
    }
}

// ---------------- K3b: anchor GEMM + fused combine -> out ----------------
__global__ void __launch_bounds__(256, 2) anchor_cls(
    const float* __restrict__ cb0,
    const float* __restrict__ cg,  const float* __restrict__ cbe,
    const float* __restrict__ cm,  const float* __restrict__ cv,
    const float* __restrict__ cw1, const float* __restrict__ cb1,
    float* __restrict__ out)
{
    extern __shared__ char smb[];
    int b = blockIdx.z;
    int i0 = blockIdx.y * 16, j0 = blockIdx.x * 8;
    cls_core(&g_A[0][b][0][0], &g_A[1][b][0][0], i0, j0,
             cb0, cg, cbe, cm, cv, cw1, cb1, smb);
    float* logit = (float*)(smb + OFF_LG);
    int t = threadIdx.x;
    if (t < 128){
        float sc = 1.f / (1.f + expf(-logit[t]));
        int i = i0 + (t >> 3), j = j0 + (t & 7);
        int ia0 = g_Idx[0][b][i][0], ia1 = g_Idx[0][b][i][1], ia2 = g_Idx[0][b][i][2];
        int jb0 = g_Idx[1][b][j][0], jb1 = g_Idx[1][b][j][1], jb2 = g_Idx[1][b][j][2];
        float s = g_Sr[b][ia0][jb0] + g_Sr[b][ia1][jb1] + g_Sr[b][ia2][jb2];
        out[(b * N + i) * N + j] = 0.5f * sc + (1.f / 6.f) * s;
    }
}

// ---------------- launch ----------------
extern "C" void kernel_launch(void* const* d_in, const int* in_sizes, int n_in,
                              void* d_out, int out_size){
    const float* f1  = (const float*)d_in[0];
    const float* f2  = (const float*)d_in[1];
    const float* sw0 = (const float*)d_in[2];
    const float* sb0 = (const float*)d_in[3];
    const float* sg  = (const float*)d_in[4];
    const float* sbe = (const float*)d_in[5];
    const float* smn = (const float*)d_in[6];
    const float* sv  = (const float*)d_in[7];
    const float* sw1 = (const float*)d_in[8];
    /* d_in[9] = sim_b1: rank-invariant, unused */
    const float* cw0 = (const float*)d_in[10];
    const float* cb0 = (const float*)d_in[11];
    const float* cg  = (const float*)d_in[12];
    const float* cbe = (const float*)d_in[13];
    const float* cm  = (const float*)d_in[14];
    const float* cv  = (const float*)d_in[15];
    const float* cw1 = (const float*)d_in[16];
    const float* cb1 = (const float*)d_in[17];
    float* out = (float*)d_out;

    cudaFuncSetAttribute(raw_cls, cudaFuncAttributeMaxDynamicSharedMemorySize, SMEM_BYTES);
    cudaFuncSetAttribute(anchor_cls, cudaFuncAttributeMaxDynamicSharedMemorySize, SMEM_BYTES);

    proj_kernel<<<576, 256>>>(f1, f2, sw0, cw0);
    topk_kernel<<<256, 256>>>(f1, f2, sb0, sg, sbe, smn, sv, sw1);
    dim3 grid(32, 16, 2);
    raw_cls<<<grid, 256, SMEM_BYTES>>>(f1, f2, cb0, cg, cbe, cm, cv, cw1, cb1);
    anchor_cls<<<grid, 256, SMEM_BYTES>>>(cb0, cg, cbe, cm, cv, cw1, cb1, out);
}

// round 14
// speedup vs baseline: 1.1285x; 1.0800x over previous
#include <cuda_runtime.h>
#include <cuda_fp16.h>
#include <cstdint>
#include <math.h>

#define D   128
#define N   256
#define BSZ 2
#define KNB 3
#define EPSF 1e-5f
#define NEG_INF (-3.402823466e38f)

// ---------------- scratch (no allocs allowed) ----------------
__device__ float g_P [2][BSZ][N][D];
__device__ float g_Q [2][BSZ][N][D];
__device__ float g_A [2][BSZ][N][D];
__device__ int   g_Idx[2][BSZ][N][KNB];
__device__ float g_S [2][BSZ][N][N];   // [0]=anchor sigmoid, [1]=raw-pair sigmoid
__device__ __half g_Wh[D * D];         // W0^T as fp16: g_Wh[d*128 + k] = cw0[k*128 + d]

// ---------------- mma.sync / ldmatrix helpers (fp16, m16n8k16) ----------------
__device__ __forceinline__ void mma16(float c[4], const uint32_t a[4],
                                      uint32_t b0, uint32_t b1){
    asm volatile(
        "mma.sync.aligned.m16n8k16.row.col.f32.f16.f16.f32 "
        "{%0,%1,%2,%3}, {%4,%5,%6,%7}, {%8,%9}, {%0,%1,%2,%3};\n"
        : "+f"(c[0]), "+f"(c[1]), "+f"(c[2]), "+f"(c[3])
        : "r"(a[0]), "r"(a[1]), "r"(a[2]), "r"(a[3]), "r"(b0), "r"(b1));
}

__device__ __forceinline__ void ldm4(uint32_t r[4], uint32_t addr){
    asm volatile("ldmatrix.sync.aligned.m8n8.x4.shared.b16 {%0,%1,%2,%3}, [%4];"
        : "=r"(r[0]), "=r"(r[1]), "=r"(r[2]), "=r"(r[3]) : "r"(addr));
}

__device__ __forceinline__ uint32_t ad2(uint32_t a, uint32_t b){
    __half2 ha = *reinterpret_cast<__half2*>(&a);
    __half2 hb = *reinterpret_cast<__half2*>(&b);
    __half2 r  = __habs2(__hsub2(ha, hb));
    return *reinterpret_cast<uint32_t*>(&r);
}

// butterfly argmax (greater, tie -> lower index); all lanes converge
__device__ __forceinline__ void warp_amax(float& v, int& idx){
    #pragma unroll
    for (int off = 16; off; off >>= 1){
        float ov = __shfl_xor_sync(0xffffffffu, v, off);
        int   oi = __shfl_xor_sync(0xffffffffu, idx, off);
        if (ov > v || (ov == v && oi < idx)){ v = ov; idx = oi; }
    }
}

// ---------------- K1: P/Q projections (512 blocks, c-split) + W prep (64 blocks) ----------------
__global__ void __launch_bounds__(256) proj_kernel(
        const float* __restrict__ f1, const float* __restrict__ f2,
        const float* __restrict__ sw0, const float* __restrict__ cw0){
    if (blockIdx.x >= 512){
        int e = (blockIdx.x - 512) * 256 + threadIdx.x;   // 64 blocks x 256 = 16384
        int d = e >> 7, k = e & 127;
        g_Wh[d * D + k] = __float2half_rn(cw0[k * D + d]);
        return;
    }
    __shared__ float fs[4][D];
    __shared__ float part[4][D];
    int which = blockIdx.x >> 8;              // 0 -> P, 1 -> Q
    int grp = blockIdx.x & 255;
    int f = grp >> 7, b = (grp >> 6) & 1, i0 = (grp & 63) * 4;
    const float* featb = (f == 0 ? f1 : f2) + b * N * D;
    int t = threadIdx.x;
    int d = t & 127, h = t >> 7;              // h = c-half
    for (int e = t; e < 4 * D; e += 256){
        int r = e >> 7, c = e & 127;
        fs[r][c] = featb[(i0 + r) * D + c];
    }
    __syncthreads();
    const float* wb = sw0 + which * D * D + d;
    int c0 = h * 64;
    float a0 = 0.f, a1 = 0.f, a2 = 0.f, a3 = 0.f;
    #pragma unroll 8
    for (int c = c0; c < c0 + 64; c++){
        float w = wb[c * D];
        a0 = fmaf(fs[0][c], w, a0);
        a1 = fmaf(fs[1][c], w, a1);
        a2 = fmaf(fs[2][c], w, a2);
        a3 = fmaf(fs[3][c], w, a3);
    }
    if (h == 1){
        part[0][d] = a0; part[1][d] = a1; part[2][d] = a2; part[3][d] = a3;
    }
    __syncthreads();
    if (h == 0){
        float* dst = which ? &g_Q[f][b][0][0] : &g_P[f][b][0][0];
        dst[(i0    ) * D + d] = a0 + part[0][d];
        dst[(i0 + 1) * D + d] = a1 + part[1][d];
        dst[(i0 + 2) * D + d] = a2 + part[2][d];
        dst[(i0 + 3) * D + d] = a3 + part[3][d];
    }
}

// ---------------- K2: 4 i's per block: sim rows -> top3 (2 syncs) -> absorb + indices ----------------
__global__ void topk_kernel(const float* __restrict__ f1, const float* __restrict__ f2,
        const float* __restrict__ sb0, const float* __restrict__ sg,
        const float* __restrict__ sbe, const float* __restrict__ smn,
        const float* __restrict__ sv,  const float* __restrict__ sw1){
    int gb = blockIdx.x;                       // 256 blocks
    int f = gb >> 7, b = (gb >> 6) & 1, i0 = (gb & 63) * 4;
    __shared__ float Ps[4][D], ss[D], tt[D], w1s[D];
    __shared__ float cv_[4][8][KNB];
    __shared__ int   ci_[4][8][KNB];
    __shared__ int   bidx[4][KNB];
    int t = threadIdx.x, lane = t & 31, warp = t >> 5;
    if (t < D){
        float s = sg[t] * rsqrtf(sv[t] + EPSF);
        ss[t]  = s;
        tt[t]  = (sb0[t] - smn[t]) * s + sbe[t];
        w1s[t] = sw1[t];
        #pragma unroll
        for (int r = 0; r < 4; r++) Ps[r][t] = g_P[f][b][i0 + r][t];
    }
    __syncthreads();
    const float* Qrow = &g_Q[f][b][t][0];
    float simv[4] = {0.f, 0.f, 0.f, 0.f};
    #pragma unroll 4
    for (int d = 0; d < D; d += 4){
        float4 q = *(const float4*)(Qrow + d);
        float s0 = ss[d], s1 = ss[d+1], s2 = ss[d+2], s3 = ss[d+3];
        float t0 = tt[d], t1 = tt[d+1], t2 = tt[d+2], t3 = tt[d+3];
        float w0 = w1s[d], w1 = w1s[d+1], w2 = w1s[d+2], w3 = w1s[d+3];
        #pragma unroll
        for (int r = 0; r < 4; r++){
            float h0 = (Ps[r][d]   + q.x) * s0 + t0;
            float h1 = (Ps[r][d+1] + q.y) * s1 + t1;
            float h2 = (Ps[r][d+2] + q.z) * s2 + t2;
            float h3 = (Ps[r][d+3] + q.w) * s3 + t3;
            simv[r] += fmaxf(h0, 0.f) * w0 + fmaxf(h1, 0.f) * w1
                     + fmaxf(h2, 0.f) * w2 + fmaxf(h3, 0.f) * w3;
        }
    }
    #pragma unroll
    for (int r = 0; r < 4; r++) if (t == i0 + r) simv[r] = NEG_INF;   // exclude self

    #pragma unroll
    for (int r = 0; r < 4; r++){
        float v = simv[r];
        #pragma unroll
        for (int k = 0; k < KNB; k++){
            float mv = v; int mi = t;
            warp_amax(mv, mi);
            if (lane == 0){ cv_[r][warp][k] = mv; ci_[r][warp][k] = mi; }
            if (t == mi) v = NEG_INF;
        }
    }
    __syncthreads();
    if (warp == 0){
        #pragma unroll
        for (int r = 0; r < 4; r++){
            float v = (lane < 24) ? cv_[r][lane / KNB][lane % KNB] : NEG_INF;
            int idx = (lane < 24) ? ci_[r][lane / KNB][lane % KNB] : 0x7fffffff;
            #pragma unroll
            for (int k = 0; k < KNB; k++){
                float mv = v; int mi = idx;
                warp_amax(mv, mi);
                if (lane == 0) bidx[r][k] = mi;
                if (idx == mi) v = NEG_INF;
            }
        }
    }
    __syncthreads();
    const float* featb = (f == 0 ? f1 : f2) + b * N * D;
    if (t < D){
        #pragma unroll
        for (int r = 0; r < 4; r++){
            int i = i0 + r;
            int k0 = bidx[r][0], k1 = bidx[r][1], k2 = bidx[r][2];
            float n0 = featb[k0 * D + t], n1 = featb[k1 * D + t], n2 = featb[k2 * D + t];
            g_A[f][b][i][t] = featb[i * D + t] + 0.5f * ((n0 + n1 + n2) * (1.f / 3.f));
        }
    }
    if (t < 4){
        #pragma unroll
        for (int k = 0; k < KNB; k++)
            g_Idx[f][b][i0 + t][k] = bidx[t][k];
    }
}

// ---------------- K3: pair-sigmoid GEMM, ch-loop (both channels per block) ----------------
// XOR-swizzled smem: logical (row, chunk[16B]) -> phys row*256 + (chunk ^ (row&7))*16
#define OFF_PS   0
#define OFF_PT   512
#define OFF_PW   1024
#define OFF_LG   1536     // 128 floats
#define OFF_US   2048     // Ush2: 16 x 68 uint32 = 4352
#define OFF_VS   6400     // Vsh2:  8 x 68 uint32 = 2176
#define OFF_WT   8704     // Wt swizzled fp16 [128 d][128 k] = 32768
#define OFF_XS   41472    // Xs swizzled fp16 [128 pair][128 k] = 32768
#define SMEM_BYTES 74240
#define UPAD 68

__global__ void __launch_bounds__(256, 2) cls_kernel(
    const float* __restrict__ f1,  const float* __restrict__ f2,
    const float* __restrict__ cb0,
    const float* __restrict__ cg,  const float* __restrict__ cbe,
    const float* __restrict__ cm,  const float* __restrict__ cv,
    const float* __restrict__ cw1, const float* __restrict__ cb1)
{
    extern __shared__ char smb[];
    float*    ps    = (float*)   (smb + OFF_PS);
    float*    pt    = (float*)   (smb + OFF_PT);
    float*    pw1   = (float*)   (smb + OFF_PW);
    float*    logit = (float*)   (smb + OFF_LG);
    uint32_t* Ush2  = (uint32_t*)(smb + OFF_US);
    uint32_t* Vsh2  = (uint32_t*)(smb + OFF_VS);
    char*     Xs    = smb + OFF_XS;
    uint32_t smem_base = (uint32_t)__cvta_generic_to_shared(smb);
    uint32_t wt_s = smem_base + OFF_WT;
    uint32_t xs_s = smem_base + OFF_XS;

    int t = threadIdx.x;
    int b = blockIdx.z;
    int i0 = blockIdx.y * 16, j0 = blockIdx.x * 8;
    int lane = t & 31, warp = t >> 5;
    int gid = lane >> 2, tig = lane & 3;
    int pg = warp >> 1, dg = warp & 1;        // 4 pair-groups (32 pairs) x 2 d-groups (64 d)

    // stage swizzled Wt from prepped fp16 (once per block)
    #pragma unroll
    for (int i = 0; i < 8; i++){
        int e = t + i * 256;                  // 2048 16B chunks
        int d = e >> 4, ck = e & 15;
        uint4 v = *(const uint4*)(g_Wh + d * D + ck * 8);
        *(uint4*)(smb + OFF_WT + d * 256 + ((ck ^ (d & 7)) << 4)) = v;
    }
    if (t < D){
        float s = cg[t] * rsqrtf(cv[t] + EPSF);
        ps[t]  = s;
        pt[t]  = (cb0[t] - cm[t]) * s + cbe[t];
        pw1[t] = cw1[t];
    }
    float b1v = cb1[0];

    // A (Xs) ldmatrix: two m-tiles (16 pairs each)
    int a_row0 = pg * 32 + (lane & 15);
    int a_row1 = a_row0 + 16;
    uint32_t a0_base = xs_s + a_row0 * 256;
    uint32_t a1_base = xs_s + a_row1 * 256;
    int a0_r7 = a_row0 & 7, a_hi = lane >> 4;
    int a1_r7 = a_row1 & 7;
    // B (Wt)
    int b_row_off = (lane & 7) + (((lane >> 4) & 1) << 3);
    int b_khi = (lane >> 3) & 1;
    uint32_t bw_base[4]; int bw_r7[4];
    #pragma unroll
    for (int ng = 0; ng < 4; ng++){
        int row = dg * 64 + ng * 16 + b_row_off;
        bw_base[ng] = wt_s + row * 256;
        bw_r7[ng]   = row & 7;
    }

    // build mapping: (2 i x 4 j x 16-chunk k) per thread
    int g2 = t >> 4, kO = t & 15;
    int ib = (g2 >> 1) * 2;
    int jb = (g2 & 1) * 4;

    #pragma unroll 1
    for (int ch = 0; ch < 2; ch++){
        const float* Ubase = (ch == 0) ? &g_A[0][b][0][0] : (f1 + b * N * D);
        const float* Vbase = (ch == 0) ? &g_A[1][b][0][0] : (f2 + b * N * D);

        __syncthreads();   // prev channel's Xs reads + logit reads complete
        for (int e = t; e < 16 * 64; e += 256){
            int r = e >> 6, c = e & 63;
            float2 fu = *(const float2*)(Ubase + (i0 + r) * D + 2 * c);
            __half2 hu = __floats2half2_rn(fu.x, fu.y);
            Ush2[r * UPAD + c] = *(uint32_t*)&hu;
        }
        for (int e = t; e < 8 * 64; e += 256){
            int r = e >> 6, c = e & 63;
            float2 fv = *(const float2*)(Vbase + (j0 + r) * D + 2 * c);
            __half2 hv = __floats2half2_rn(fv.x, fv.y);
            Vsh2[r * UPAD + c] = *(uint32_t*)&hv;
        }
        if (t < 128) logit[t] = b1v;
        __syncthreads();

        // build X = |U_i - V_j| into swizzled tile: 8 STS.128 per thread
        {
            uint4 u0 = *(const uint4*)(Ush2 +  ib      * UPAD + kO * 4);
            uint4 u1 = *(const uint4*)(Ush2 + (ib + 1) * UPAD + kO * 4);
            #pragma unroll
            for (int jj = 0; jj < 4; jj++){
                uint4 v = *(const uint4*)(Vsh2 + (jb + jj) * UPAD + kO * 4);
                uint4 x0, x1;
                x0.x = ad2(u0.x, v.x); x0.y = ad2(u0.y, v.y);
                x0.z = ad2(u0.z, v.z); x0.w = ad2(u0.w, v.w);
                x1.x = ad2(u1.x, v.x); x1.y = ad2(u1.y, v.y);
                x1.z = ad2(u1.z, v.z); x1.w = ad2(u1.w, v.w);
                int p0 =  ib      * 8 + jb + jj;
                int p1 = (ib + 1) * 8 + jb + jj;
                *(uint4*)(Xs + p0 * 256 + ((kO ^ (p0 & 7)) << 4)) = x0;
                *(uint4*)(Xs + p1 * 256 + ((kO ^ (p1 & 7)) << 4)) = x1;
            }
        }
        __syncthreads();

        float cacc[2][8][4];
        #pragma unroll
        for (int mt = 0; mt < 2; mt++)
            #pragma unroll
            for (int nt = 0; nt < 8; nt++)
                #pragma unroll
                for (int q = 0; q < 4; q++) cacc[mt][nt][q] = 0.f;

        #pragma unroll 2
        for (int ks = 0; ks < 8; ks++){
            int ck = 2 * ks;
            uint32_t aX0[4], aX1[4];
            ldm4(aX0, a0_base + (((ck + a_hi) ^ a0_r7) << 4));
            ldm4(aX1, a1_base + (((ck + a_hi) ^ a1_r7) << 4));
            #pragma unroll
            for (int ng = 0; ng < 4; ng++){
                uint32_t bW[4];
                ldm4(bW, bw_base[ng] + (((ck + b_khi) ^ bw_r7[ng]) << 4));
                mma16(cacc[0][ng * 2],     aX0, bW[0], bW[1]);
                mma16(cacc[0][ng * 2 + 1], aX0, bW[2], bW[3]);
                mma16(cacc[1][ng * 2],     aX1, bW[0], bW[1]);
                mma16(cacc[1][ng * 2 + 1], aX1, bW[2], bW[3]);
            }
        }

        // epilogue: rows = pairs, cols = d (this warp's 64-d half); reduce d in-thread
        #pragma unroll
        for (int mt = 0; mt < 2; mt++){
            float l0 = 0.f, l1 = 0.f;
            #pragma unroll
            for (int nt = 0; nt < 8; nt++){
                int d0 = dg * 64 + (nt >> 1) * 16 + (nt & 1) * 8 + 2 * tig;
                float s0 = ps[d0], t0 = pt[d0], w0 = pw1[d0];
                float s1 = ps[d0 + 1], t1 = pt[d0 + 1], w1 = pw1[d0 + 1];
                float* c = cacc[mt][nt];
                l0 += fmaxf(c[0] * s0 + t0, 0.f) * w0 + fmaxf(c[1] * s1 + t1, 0.f) * w1;
                l1 += fmaxf(c[2] * s0 + t0, 0.f) * w0 + fmaxf(c[3] * s1 + t1, 0.f) * w1;
            }
            l0 += __shfl_xor_sync(0xffffffffu, l0, 1);
            l0 += __shfl_xor_sync(0xffffffffu, l0, 2);
            l1 += __shfl_xor_sync(0xffffffffu, l1, 1);
            l1 += __shfl_xor_sync(0xffffffffu, l1, 2);
            if (tig == 0){
                atomicAdd(&logit[pg * 32 + mt * 16 + gid],     l0);
                atomicAdd(&logit[pg * 32 + mt * 16 + gid + 8], l1);
            }
        }
        __syncthreads();
        if (t < 128){
            float sc = 1.f / (1.f + expf(-logit[t]));
            g_S[ch][b][i0 + (t >> 3)][j0 + (t & 7)] = sc;
        }
    }
}

// ---------------- K4: combine anchor + gathered neighbor scores (no syncs) ----------------
__global__ void combine_kernel(float* __restrict__ out){
    int blk = blockIdx.x;             // 512 = b*256 + i
    int b = blk >> 8, i = blk & 255;
    int j = threadIdx.x;
    int ia0 = __ldg(&g_Idx[0][b][i][0]);
    int ia1 = __ldg(&g_Idx[0][b][i][1]);
    int ia2 = __ldg(&g_Idx[0][b][i][2]);
    float sa = g_S[0][b][i][j];
    const int* bj = &g_Idx[1][b][j][0];
    int b0 = bj[0], b1 = bj[1], b2 = bj[2];
    float s = g_S[1][b][ia0][b0] + g_S[1][b][ia1][b1] + g_S[1][b][ia2][b2];
    out[(b * N + i) * N + j] = 0.5f * sa + (1.f / 6.f) * s;
}

// ---------------- launch ----------------
extern "C" void kernel_launch(void* const* d_in, const int* in_sizes, int n_in,
                              void* d_out, int out_size){
    const float* f1  = (const float*)d_in[0];
    const float* f2  = (const float*)d_in[1];
    const float* sw0 = (const float*)d_in[2];
    const float* sb0 = (const float*)d_in[3];
    const float* sg  = (const float*)d_in[4];
    const float* sbe = (const float*)d_in[5];
    const float* smn = (const float*)d_in[6];
    const float* sv  = (const float*)d_in[7];
    const float* sw1 = (const float*)d_in[8];
    /* d_in[9] = sim_b1: rank-invariant, unused */
    const float* cw0 = (const float*)d_in[10];
    const float* cb0 = (const float*)d_in[11];
    const float* cg  = (const float*)d_in[12];
    const float* cbe = (const float*)d_in[13];
    const float* cm  = (const float*)d_in[14];
    const float* cv  = (const float*)d_in[15];
    const float* cw1 = (const float*)d_in[16];
    const float* cb1 = (const float*)d_in[17];
    float* out = (float*)d_out;

    cudaFuncSetAttribute(cls_kernel, cudaFuncAttributeMaxDynamicSharedMemorySize,
                         SMEM_BYTES);

    proj_kernel<<<576, 256>>>(f1, f2, sw0, cw0);
    topk_kernel<<<256, 256>>>(f1, f2, sb0, sg, sbe, smn, sv, sw1);
    dim3 grid(32, 16, 2);
    cls_kernel<<<grid, 256, SMEM_BYTES>>>(
        f1, f2, cb0, cg, cbe, cm, cv, cw1, cb1);
    combine_kernel<<<512, 256>>>(out);
}

// round 15
// speedup vs baseline: 1.1340x; 1.0049x over previous
#include <cuda_runtime.h>
#include <cuda_fp16.h>
#include <cstdint>
#include <math.h>

#define D   128
#define N   256
#define BSZ 2
#define KNB 3
#define EPSF 1e-5f
#define NEG_INF (-3.402823466e38f)

// ---------------- scratch (no allocs allowed) ----------------
__device__ float g_P [2][BSZ][N][D];
__device__ float g_Q [2][BSZ][N][D];
__device__ float g_A [2][BSZ][N][D];
__device__ int   g_Idx[2][BSZ][N][KNB];
__device__ float g_S [2][BSZ][N][N];   // [0]=anchor sigmoid, [1]=raw-pair sigmoid
__device__ __half g_Wh[D * D];         // W0^T as fp16: g_Wh[d*128 + k] = cw0[k*128 + d]

// ---------------- mma.sync / ldmatrix helpers (fp16, m16n8k16) ----------------
__device__ __forceinline__ void mma16(float c[4], const uint32_t a[4],
                                      uint32_t b0, uint32_t b1){
    asm volatile(
        "mma.sync.aligned.m16n8k16.row.col.f32.f16.f16.f32 "
        "{%0,%1,%2,%3}, {%4,%5,%6,%7}, {%8,%9}, {%0,%1,%2,%3};\n"
        : "+f"(c[0]), "+f"(c[1]), "+f"(c[2]), "+f"(c[3])
        : "r"(a[0]), "r"(a[1]), "r"(a[2]), "r"(a[3]), "r"(b0), "r"(b1));
}

__device__ __forceinline__ void ldm4(uint32_t r[4], uint32_t addr){
    asm volatile("ldmatrix.sync.aligned.m8n8.x4.shared.b16 {%0,%1,%2,%3}, [%4];"
        : "=r"(r[0]), "=r"(r[1]), "=r"(r[2]), "=r"(r[3]) : "r"(addr));
}

__device__ __forceinline__ uint32_t ad2(uint32_t a, uint32_t b){
    __half2 ha = *reinterpret_cast<__half2*>(&a);
    __half2 hb = *reinterpret_cast<__half2*>(&b);
    __half2 r  = __habs2(__hsub2(ha, hb));
    return *reinterpret_cast<uint32_t*>(&r);
}

// butterfly argmax (greater, tie -> lower index); all lanes converge
__device__ __forceinline__ void warp_amax(float& v, int& idx){
    #pragma unroll
    for (int off = 16; off; off >>= 1){
        float ov = __shfl_xor_sync(0xffffffffu, v, off);
        int   oi = __shfl_xor_sync(0xffffffffu, idx, off);
        if (ov > v || (ov == v && oi < idx)){ v = ov; idx = oi; }
    }
}

// ---------------- K1: P/Q projections (512 blocks, c-split) + W prep (64 blocks) ----------------
__global__ void __launch_bounds__(256) proj_kernel(
        const float* __restrict__ f1, const float* __restrict__ f2,
        const float* __restrict__ sw0, const float* __restrict__ cw0){
    if (blockIdx.x >= 512){
        int e = (blockIdx.x - 512) * 256 + threadIdx.x;   // 64 blocks x 256 = 16384
        int d = e >> 7, k = e & 127;
        g_Wh[d * D + k] = __float2half_rn(cw0[k * D + d]);
        return;
    }
    __shared__ float fs[4][D];
    __shared__ float part[4][D];
    int which = blockIdx.x >> 8;              // 0 -> P, 1 -> Q
    int grp = blockIdx.x & 255;
    int f = grp >> 7, b = (grp >> 6) & 1, i0 = (grp & 63) * 4;
    const float* featb = (f == 0 ? f1 : f2) + b * N * D;
    int t = threadIdx.x;
    int d = t & 127, h = t >> 7;              // h = c-half
    for (int e = t; e < 4 * D; e += 256){
        int r = e >> 7, c = e & 127;
        fs[r][c] = featb[(i0 + r) * D + c];
    }
    __syncthreads();
    const float* wb = sw0 + which * D * D + d;
    int c0 = h * 64;
    float a0 = 0.f, a1 = 0.f, a2 = 0.f, a3 = 0.f;
    #pragma unroll 8
    for (int c = c0; c < c0 + 64; c++){
        float w = wb[c * D];
        a0 = fmaf(fs[0][c], w, a0);
        a1 = fmaf(fs[1][c], w, a1);
        a2 = fmaf(fs[2][c], w, a2);
        a3 = fmaf(fs[3][c], w, a3);
    }
    if (h == 1){
        part[0][d] = a0; part[1][d] = a1; part[2][d] = a2; part[3][d] = a3;
    }
    __syncthreads();
    if (h == 0){
        float* dst = which ? &g_Q[f][b][0][0] : &g_P[f][b][0][0];
        dst[(i0    ) * D + d] = a0 + part[0][d];
        dst[(i0 + 1) * D + d] = a1 + part[1][d];
        dst[(i0 + 2) * D + d] = a2 + part[2][d];
        dst[(i0 + 3) * D + d] = a3 + part[3][d];
    }
}

// ---------------- K2: 4 i's per block: sim rows -> top3 (2 syncs) -> absorb + indices ----------------
__global__ void topk_kernel(const float* __restrict__ f1, const float* __restrict__ f2,
        const float* __restrict__ sb0, const float* __restrict__ sg,
        const float* __restrict__ sbe, const float* __restrict__ smn,
        const float* __restrict__ sv,  const float* __restrict__ sw1){
    int gb = blockIdx.x;                       // 256 blocks
    int f = gb >> 7, b = (gb >> 6) & 1, i0 = (gb & 63) * 4;
    __shared__ float Ps[4][D], ss[D], tt[D], w1s[D];
    __shared__ float cv_[4][8][KNB];
    __shared__ int   ci_[4][8][KNB];
    __shared__ int   bidx[4][KNB];
    int t = threadIdx.x, lane = t & 31, warp = t >> 5;
    if (t < D){
        float s = sg[t] * rsqrtf(sv[t] + EPSF);
        ss[t]  = s;
        tt[t]  = (sb0[t] - smn[t]) * s + sbe[t];
        w1s[t] = sw1[t];
        #pragma unroll
        for (int r = 0; r < 4; r++) Ps[r][t] = g_P[f][b][i0 + r][t];
    }
    __syncthreads();
    const float* Qrow = &g_Q[f][b][t][0];
    float simv[4] = {0.f, 0.f, 0.f, 0.f};
    #pragma unroll 4
    for (int d = 0; d < D; d += 4){
        float4 q = *(const float4*)(Qrow + d);
        float s0 = ss[d], s1 = ss[d+1], s2 = ss[d+2], s3 = ss[d+3];
        float t0 = tt[d], t1 = tt[d+1], t2 = tt[d+2], t3 = tt[d+3];
        float w0 = w1s[d], w1 = w1s[d+1], w2 = w1s[d+2], w3 = w1s[d+3];
        #pragma unroll
        for (int r = 0; r < 4; r++){
            float h0 = (Ps[r][d]   + q.x) * s0 + t0;
            float h1 = (Ps[r][d+1] + q.y) * s1 + t1;
            float h2 = (Ps[r][d+2] + q.z) * s2 + t2;
            float h3 = (Ps[r][d+3] + q.w) * s3 + t3;
            simv[r] += fmaxf(h0, 0.f) * w0 + fmaxf(h1, 0.f) * w1
                     + fmaxf(h2, 0.f) * w2 + fmaxf(h3, 0.f) * w3;
        }
    }
    #pragma unroll
    for (int r = 0; r < 4; r++) if (t == i0 + r) simv[r] = NEG_INF;   // exclude self

    #pragma unroll
    for (int r = 0; r < 4; r++){
        float v = simv[r];
        #pragma unroll
        for (int k = 0; k < KNB; k++){
            float mv = v; int mi = t;
            warp_amax(mv, mi);
            if (lane == 0){ cv_[r][warp][k] = mv; ci_[r][warp][k] = mi; }
            if (t == mi) v = NEG_INF;
        }
    }
    __syncthreads();
    if (warp == 0){
        #pragma unroll
        for (int r = 0; r < 4; r++){
            float v = (lane < 24) ? cv_[r][lane / KNB][lane % KNB] : NEG_INF;
            int idx = (lane < 24) ? ci_[r][lane / KNB][lane % KNB] : 0x7fffffff;
            #pragma unroll
            for (int k = 0; k < KNB; k++){
                float mv = v; int mi = idx;
                warp_amax(mv, mi);
                if (lane == 0) bidx[r][k] = mi;
                if (idx == mi) v = NEG_INF;
            }
        }
    }
    __syncthreads();
    const float* featb = (f == 0 ? f1 : f2) + b * N * D;
    if (t < D){
        #pragma unroll
        for (int r = 0; r < 4; r++){
            int i = i0 + r;
            int k0 = bidx[r][0], k1 = bidx[r][1], k2 = bidx[r][2];
            float n0 = featb[k0 * D + t], n1 = featb[k1 * D + t], n2 = featb[k2 * D + t];
            g_A[f][b][i][t] = featb[i * D + t] + 0.5f * ((n0 + n1 + n2) * (1.f / 3.f));
        }
    }
    if (t < 4){
        #pragma unroll
        for (int k = 0; k < KNB; k++)
            g_Idx[f][b][i0 + t][k] = bidx[t][k];
    }
}

// ---------------- K3: dual-channel-resident pair-sigmoid GEMM ----------------
// XOR-swizzled operand tiles: logical (row, chunk[16B]) -> phys row*256 + (chunk ^ (row&7))*16
#define OFF_PS   0
#define OFF_PT   512
#define OFF_PW   1024
#define OFF_LG   1536     // 256 floats (logit0 | logit1)
#define OFF_US   2560     // Ush2: 2ch x 16 x 68 uint32 = 8704
#define OFF_VS   11264    // Vsh2: 2ch x  8 x 68 uint32 = 4352
#define OFF_WT   15616    // Wt swizzled fp16 [128 d][128 k] = 32768
#define OFF_XS   48384    // Xs swizzled fp16 2ch x [128 pair][128 k] = 65536
#define SMEM_BYTES 113920
#define UPAD 68

__global__ void __launch_bounds__(256, 2) cls_kernel(
    const float* __restrict__ f1,  const float* __restrict__ f2,
    const float* __restrict__ cb0,
    const float* __restrict__ cg,  const float* __restrict__ cbe,
    const float* __restrict__ cm,  const float* __restrict__ cv,
    const float* __restrict__ cw1, const float* __restrict__ cb1)
{
    extern __shared__ char smb[];
    float*    ps    = (float*)   (smb + OFF_PS);
    float*    pt    = (float*)   (smb + OFF_PT);
    float*    pw1   = (float*)   (smb + OFF_PW);
    float*    logit = (float*)   (smb + OFF_LG);   // [2][128]
    uint32_t* Ush2  = (uint32_t*)(smb + OFF_US);   // ch*1088 + r*68 + c
    uint32_t* Vsh2  = (uint32_t*)(smb + OFF_VS);   // ch*544  + r*68 + c
    char*     Xs    = smb + OFF_XS;                // ch*32768 + swizzled
    uint32_t smem_base = (uint32_t)__cvta_generic_to_shared(smb);
    uint32_t wt_s = smem_base + OFF_WT;
    uint32_t xs_s = smem_base + OFF_XS;

    int t = threadIdx.x;
    int b = blockIdx.z;
    int i0 = blockIdx.y * 16, j0 = blockIdx.x * 8;
    int lane = t & 31, warp = t >> 5;
    int gid = lane >> 2, tig = lane & 3;
    int pg = warp >> 1, dg = warp & 1;        // 4 pair-groups (32 pairs) x 2 d-groups (64 d)

    // stage swizzled Wt from prepped fp16 (once per block)
    #pragma unroll
    for (int i = 0; i < 8; i++){
        int e = t + i * 256;                  // 2048 16B chunks
        int d = e >> 4, ck = e & 15;
        uint4 v = *(const uint4*)(g_Wh + d * D + ck * 8);
        *(uint4*)(smb + OFF_WT + d * 256 + ((ck ^ (d & 7)) << 4)) = v;
    }
    if (t < D){
        float s = cg[t] * rsqrtf(cv[t] + EPSF);
        ps[t]  = s;
        pt[t]  = (cb0[t] - cm[t]) * s + cbe[t];
        pw1[t] = cw1[t];
    }
    logit[t] = cb1[0];                        // all 256 entries (2 channels)

    // stage U/V for BOTH channels (independent LDGs -> deep MLP, one phase)
    #pragma unroll
    for (int ch = 0; ch < 2; ch++){
        const float* Ubase = (ch == 0) ? &g_A[0][b][0][0] : (f1 + b * N * D);
        const float* Vbase = (ch == 0) ? &g_A[1][b][0][0] : (f2 + b * N * D);
        for (int e = t; e < 16 * 64; e += 256){
            int r = e >> 6, c = e & 63;
            float2 fu = *(const float2*)(Ubase + (i0 + r) * D + 2 * c);
            __half2 hu = __floats2half2_rn(fu.x, fu.y);
            Ush2[ch * 1088 + r * UPAD + c] = *(uint32_t*)&hu;
        }
        for (int e = t; e < 8 * 64; e += 256){
            int r = e >> 6, c = e & 63;
            float2 fv = *(const float2*)(Vbase + (j0 + r) * D + 2 * c);
            __half2 hv = __floats2half2_rn(fv.x, fv.y);
            Vsh2[ch * 544 + r * UPAD + c] = *(uint32_t*)&hv;
        }
    }
    __syncthreads();

    // build BOTH X tiles: 16 STS.128 per thread, no intervening barrier
    {
        int g2 = t >> 4, kO = t & 15;
        int ib = (g2 >> 1) * 2;
        int jb = (g2 & 1) * 4;
        #pragma unroll
        for (int ch = 0; ch < 2; ch++){
            char* Xc = Xs + ch * 32768;
            uint4 u0 = *(const uint4*)(Ush2 + ch * 1088 +  ib      * UPAD + kO * 4);
            uint4 u1 = *(const uint4*)(Ush2 + ch * 1088 + (ib + 1) * UPAD + kO * 4);
            #pragma unroll
            for (int jj = 0; jj < 4; jj++){
                uint4 v = *(const uint4*)(Vsh2 + ch * 544 + (jb + jj) * UPAD + kO * 4);
                uint4 x0, x1;
                x0.x = ad2(u0.x, v.x); x0.y = ad2(u0.y, v.y);
                x0.z = ad2(u0.z, v.z); x0.w = ad2(u0.w, v.w);
                x1.x = ad2(u1.x, v.x); x1.y = ad2(u1.y, v.y);
                x1.z = ad2(u1.z, v.z); x1.w = ad2(u1.w, v.w);
                int p0 =  ib      * 8 + jb + jj;
                int p1 = (ib + 1) * 8 + jb + jj;
                *(uint4*)(Xc + p0 * 256 + ((kO ^ (p0 & 7)) << 4)) = x0;
                *(uint4*)(Xc + p1 * 256 + ((kO ^ (p1 & 7)) << 4)) = x1;
            }
        }
    }
    __syncthreads();

    // ldmatrix lane addressing (channel-invariant parts)
    int a_row0 = pg * 32 + (lane & 15);
    int a_row1 = a_row0 + 16;
    int a0_r7 = a_row0 & 7, a_hi = lane >> 4;
    int a1_r7 = a_row1 & 7;
    int b_row_off = (lane & 7) + (((lane >> 4) & 1) << 3);
    int b_khi = (lane >> 3) & 1;
    uint32_t bw_base[4]; int bw_r7[4];
    #pragma unroll
    for (int ng = 0; ng < 4; ng++){
        int row = dg * 64 + ng * 16 + b_row_off;
        bw_base[ng] = wt_s + row * 256;
        bw_r7[ng]   = row & 7;
    }

    // two mainloops back-to-back (no barrier: disjoint logit halves, read after final sync)
    #pragma unroll 1
    for (int ch = 0; ch < 2; ch++){
        uint32_t a0_base = xs_s + ch * 32768 + a_row0 * 256;
        uint32_t a1_base = xs_s + ch * 32768 + a_row1 * 256;

        float cacc[2][8][4];
        #pragma unroll
        for (int mt = 0; mt < 2; mt++)
            #pragma unroll
            for (int nt = 0; nt < 8; nt++)
                #pragma unroll
                for (int q = 0; q < 4; q++) cacc[mt][nt][q] = 0.f;

        #pragma unroll 2
        for (int ks = 0; ks < 8; ks++){
            int ck = 2 * ks;
            uint32_t aX0[4], aX1[4];
            ldm4(aX0, a0_base + (((ck + a_hi) ^ a0_r7) << 4));
            ldm4(aX1, a1_base + (((ck + a_hi) ^ a1_r7) << 4));
            #pragma unroll
            for (int ng = 0; ng < 4; ng++){
                uint32_t bW[4];
                ldm4(bW, bw_base[ng] + (((ck + b_khi) ^ bw_r7[ng]) << 4));
                mma16(cacc[0][ng * 2],     aX0, bW[0], bW[1]);
                mma16(cacc[0][ng * 2 + 1], aX0, bW[2], bW[3]);
                mma16(cacc[1][ng * 2],     aX1, bW[0], bW[1]);
                mma16(cacc[1][ng * 2 + 1], aX1, bW[2], bW[3]);
            }
        }

        // epilogue: reduce d in-thread, accumulate into this channel's logit half
        float* lg = logit + ch * 128;
        #pragma unroll
        for (int mt = 0; mt < 2; mt++){
            float l0 = 0.f, l1 = 0.f;
            #pragma unroll
            for (int nt = 0; nt < 8; nt++){
                int d0 = dg * 64 + (nt >> 1) * 16 + (nt & 1) * 8 + 2 * tig;
                float s0 = ps[d0], t0 = pt[d0], w0 = pw1[d0];
                float s1 = ps[d0 + 1], t1 = pt[d0 + 1], w1 = pw1[d0 + 1];
                float* c = cacc[mt][nt];
                l0 += fmaxf(c[0] * s0 + t0, 0.f) * w0 + fmaxf(c[1] * s1 + t1, 0.f) * w1;
                l1 += fmaxf(c[2] * s0 + t0, 0.f) * w0 + fmaxf(c[3] * s1 + t1, 0.f) * w1;
            }
            l0 += __shfl_xor_sync(0xffffffffu, l0, 1);
            l0 += __shfl_xor_sync(0xffffffffu, l0, 2);
            l1 += __shfl_xor_sync(0xffffffffu, l1, 1);
            l1 += __shfl_xor_sync(0xffffffffu, l1, 2);
            if (tig == 0){
                atomicAdd(&lg[pg * 32 + mt * 16 + gid],     l0);
                atomicAdd(&lg[pg * 32 + mt * 16 + gid + 8], l1);
            }
        }
    }
    __syncthreads();
    if (t < 128){
        int i = i0 + (t >> 3), j = j0 + (t & 7);
        float sc0 = 1.f / (1.f + expf(-logit[t]));
        float sc1 = 1.f / (1.f + expf(-logit[128 + t]));
        g_S[0][b][i][j] = sc0;
        g_S[1][b][i][j] = sc1;
    }
}

// ---------------- K4: combine anchor + gathered neighbor scores (no syncs) ----------------
__global__ void combine_kernel(float* __restrict__ out){
    int blk = blockIdx.x;             // 512 = b*256 + i
    int b = blk >> 8, i = blk & 255;
    int j = threadIdx.x;
    int ia0 = __ldg(&g_Idx[0][b][i][0]);
    int ia1 = __ldg(&g_Idx[0][b][i][1]);
    int ia2 = __ldg(&g_Idx[0][b][i][2]);
    float sa = g_S[0][b][i][j];
    const int* bj = &g_Idx[1][b][j][0];
    int b0 = bj[0], b1 = bj[1], b2 = bj[2];
    float s = g_S[1][b][ia0][b0] + g_S[1][b][ia1][b1] + g_S[1][b][ia2][b2];
    out[(b * N + i) * N + j] = 0.5f * sa + (1.f / 6.f) * s;
}

// ---------------- launch ----------------
extern "C" void kernel_launch(void* const* d_in, const int* in_sizes, int n_in,
                              void* d_out, int out_size){
    const float* f1  = (const float*)d_in[0];
    const float* f2  = (const float*)d_in[1];
    const float* sw0 = (const float*)d_in[2];
    const float* sb0 = (const float*)d_in[3];
    const float* sg  = (const float*)d_in[4];
    const float* sbe = (const float*)d_in[5];
    const float* smn = (const float*)d_in[6];
    const float* sv  = (const float*)d_in[7];
    const float* sw1 = (const float*)d_in[8];
    /* d_in[9] = sim_b1: rank-invariant, unused */
    const float* cw0 = (const float*)d_in[10];
    const float* cb0 = (const float*)d_in[11];
    const float* cg  = (const float*)d_in[12];
    const float* cbe = (const float*)d_in[13];
    const float* cm  = (const float*)d_in[14];
    const float* cv  = (const float*)d_in[15];
    const float* cw1 = (const float*)d_in[16];
    const float* cb1 = (const float*)d_in[17];
    float* out = (float*)d_out;

    cudaFuncSetAttribute(cls_kernel, cudaFuncAttributeMaxDynamicSharedMemorySize,
                         SMEM_BYTES);

    proj_kernel<<<576, 256>>>(f1, f2, sw0, cw0);
    topk_kernel<<<256, 256>>>(f1, f2, sb0, sg, sbe, smn, sv, sw1);
    dim3 grid(32, 16, 2);
    cls_kernel<<<grid, 256, SMEM_BYTES>>>(
        f1, f2, cb0, cg, cbe, cm, cv, cw1, cb1);
    combine_kernel<<<512, 256>>>(out);
}